// round 1
// baseline (speedup 1.0000x reference)
#include <cuda_runtime.h>
#include <math.h>

// Problem constants
#define B_    2
#define T_    2048
#define C_    4096
#define NH_   32
#define NG_   8
#define HS_   128
#define M_    (B_ * T_)                 // 4096 rows
#define NQKV_ ((NH_ + 2 * NG_) * HS_)   // 6144

// Scratch (no cudaMalloc allowed)
__device__ float g_qkv[(size_t)M_ * NQKV_];   // ~100.7 MB
__device__ float g_y[(size_t)M_ * C_];        // ~67 MB

// ---------------------------------------------------------------------------
// SGEMM: C[M,N] = A[M,K] @ B[N,K]^T   (both inputs K-major / row-major)
// 128x128 block tile, BK=16, 256 threads, 8x8 register microtile.
// All dims are multiples of 128/16 here, so no bounds checks.
// ---------------------------------------------------------------------------
__global__ __launch_bounds__(256) void sgemm_abt(
    const float* __restrict__ A, const float* __restrict__ B,
    float* __restrict__ C, int M, int N, int K)
{
    __shared__ float As[16][128];
    __shared__ float Bs[16][128];

    const int tid  = threadIdx.x;
    const int ty   = tid >> 4;        // 0..15
    const int tx   = tid & 15;        // 0..15
    const int brow = blockIdx.y * 128;
    const int bcol = blockIdx.x * 128;

    const int lr = tid >> 1;          // 0..127 (tile row to load)
    const int lc = (tid & 1) * 8;     // 0 or 8 (k-offset)

    const float* Ap = A + (size_t)(brow + lr) * K + lc;
    const float* Bp = B + (size_t)(bcol + lr) * K + lc;

    float acc[8][8];
#pragma unroll
    for (int i = 0; i < 8; i++)
#pragma unroll
        for (int j = 0; j < 8; j++) acc[i][j] = 0.f;

    for (int k0 = 0; k0 < K; k0 += 16) {
        float4 a0 = *(const float4*)(Ap + k0);
        float4 a1 = *(const float4*)(Ap + k0 + 4);
        float4 b0 = *(const float4*)(Bp + k0);
        float4 b1 = *(const float4*)(Bp + k0 + 4);
        __syncthreads();   // previous compute done before overwrite
        As[lc + 0][lr] = a0.x; As[lc + 1][lr] = a0.y; As[lc + 2][lr] = a0.z; As[lc + 3][lr] = a0.w;
        As[lc + 4][lr] = a1.x; As[lc + 5][lr] = a1.y; As[lc + 6][lr] = a1.z; As[lc + 7][lr] = a1.w;
        Bs[lc + 0][lr] = b0.x; Bs[lc + 1][lr] = b0.y; Bs[lc + 2][lr] = b0.z; Bs[lc + 3][lr] = b0.w;
        Bs[lc + 4][lr] = b1.x; Bs[lc + 5][lr] = b1.y; Bs[lc + 6][lr] = b1.z; Bs[lc + 7][lr] = b1.w;
        __syncthreads();

#pragma unroll
        for (int kk = 0; kk < 16; kk++) {
            float ar[8], br[8];
            *(float4*)(ar)     = *(const float4*)&As[kk][ty * 8];
            *(float4*)(ar + 4) = *(const float4*)&As[kk][ty * 8 + 4];
            *(float4*)(br)     = *(const float4*)&Bs[kk][tx * 8];
            *(float4*)(br + 4) = *(const float4*)&Bs[kk][tx * 8 + 4];
#pragma unroll
            for (int i = 0; i < 8; i++)
#pragma unroll
                for (int j = 0; j < 8; j++)
                    acc[i][j] += ar[i] * br[j];
        }
    }

#pragma unroll
    for (int i = 0; i < 8; i++) {
        float* cp = C + (size_t)(brow + ty * 8 + i) * N + bcol + tx * 8;
        *(float4*)(cp)     = make_float4(acc[i][0], acc[i][1], acc[i][2], acc[i][3]);
        *(float4*)(cp + 4) = make_float4(acc[i][4], acc[i][5], acc[i][6], acc[i][7]);
    }
}

// ---------------------------------------------------------------------------
// In-place RoPE on q (slots 0..3) and k (slot 4) inside g_qkv.
// One thread handles the (d, d+64) pair -> race-free in-place update.
// ---------------------------------------------------------------------------
__global__ void rope_kernel(float* __restrict__ qkv,
                            const float* __restrict__ cs,
                            const float* __restrict__ sn)
{
    int idx = blockIdx.x * blockDim.x + threadIdx.x;
    const int total = M_ * NG_ * 5 * 64;
    if (idx >= total) return;

    int d = idx & 63;
    int r = idx >> 6;
    int slot = r % 5; r /= 5;          // 0..3 = q heads, 4 = k
    int g    = r % NG_; r /= NG_;      // kv group
    // r is now the flattened (b*T + t) row
    int t = r & (T_ - 1);

    float* p = qkv + (size_t)r * NQKV_ + g * (6 * HS_) + slot * HS_;
    float x1 = p[d];
    float x2 = p[d + 64];
    float c1 = cs[t * HS_ + d],      s1 = sn[t * HS_ + d];
    float c2 = cs[t * HS_ + d + 64], s2 = sn[t * HS_ + d + 64];
    p[d]      = x1 * c1 - x2 * s1;   // rotated half 1: -x2
    p[d + 64] = x2 * c2 + x1 * s2;   // rotated half 2: +x1
}

// ---------------------------------------------------------------------------
// FP32 causal flash attention.
// Block = (q-tile of 64 rows, one (b,h)). 256 threads as 16x16.
// S microtile 4x4, O microtile 4x8. Online softmax, P staged via smem.
// smem: Qs[64][132] + KsT[128][68] + Vs[64][132] + Ps[64][64]  = 118784 B
// ---------------------------------------------------------------------------
#define ATT_SMEM_BYTES ((64 * 132 + 128 * 68 + 64 * 132 + 64 * 64) * 4)

__global__ __launch_bounds__(256) void attn_kernel(
    const float* __restrict__ qkv, float* __restrict__ y)
{
    extern __shared__ float sm[];
    float* Qs  = sm;                    // [64][132]
    float* KsT = Qs + 64 * 132;         // [128][68]  (transposed: [d][key])
    float* Vs  = KsT + 128 * 68;        // [64][132]
    float* Ps  = Vs + 64 * 132;         // [64][64]

    const int tid = threadIdx.x;
    const int ty  = tid >> 4;           // 0..15 -> S rows ty*4..+3
    const int tx  = tid & 15;           // 0..15 -> S cols tx*4..+3 / O cols tx*8..+7
    const int qt  = blockIdx.x;
    const int bh  = blockIdx.y;
    const int b   = bh >> 5;
    const int h   = bh & 31;
    const int g   = h >> 2;
    const int qi  = h & 3;

    const float* qb = qkv + (size_t)b * T_ * NQKV_ + g * 768 + qi * 128;
    const float* kb = qkv + (size_t)b * T_ * NQKV_ + g * 768 + 512;
    const float* vb = kb + 128;
    const int q0 = qt * 64;

    // Load Q tile (strided rows in gmem, row-major in smem, pad 132)
    for (int i = tid; i < 64 * 32; i += 256) {
        int r  = i >> 5;
        int c4 = (i & 31) << 2;
        *(float4*)&Qs[r * 132 + c4] =
            *(const float4*)(qb + (size_t)(q0 + r) * NQKV_ + c4);
    }

    float o[4][8];
    float mrow[4], lrow[4];
#pragma unroll
    for (int i = 0; i < 4; i++) {
        mrow[i] = -1e30f;
        lrow[i] = 0.f;
#pragma unroll
        for (int j = 0; j < 8; j++) o[i][j] = 0.f;
    }

    const float sc = 0.08838834764831845f;   // 1/sqrt(128)

    for (int kt = 0; kt <= qt; kt++) {
        const int k0 = kt * 64;
        __syncthreads();   // prior Ks/Vs/Ps reads complete

        // K tile, transposed store: KsT[d][key]
        for (int i = tid; i < 64 * 32; i += 256) {
            int r  = i & 63;            // key index (consecutive within warp)
            int c4 = (i >> 6) << 2;     // d offset
            float4 kv = *(const float4*)(kb + (size_t)(k0 + r) * NQKV_ + c4);
            KsT[(c4 + 0) * 68 + r] = kv.x;
            KsT[(c4 + 1) * 68 + r] = kv.y;
            KsT[(c4 + 2) * 68 + r] = kv.z;
            KsT[(c4 + 3) * 68 + r] = kv.w;
        }
        // V tile, row-major
        for (int i = tid; i < 64 * 32; i += 256) {
            int r  = i >> 5;
            int c4 = (i & 31) << 2;
            *(float4*)&Vs[r * 132 + c4] =
                *(const float4*)(vb + (size_t)(k0 + r) * NQKV_ + c4);
        }
        __syncthreads();

        // ---- S = Q K^T (4x4 microtile) ----
        float s[4][4];
#pragma unroll
        for (int i = 0; i < 4; i++)
#pragma unroll
            for (int j = 0; j < 4; j++) s[i][j] = 0.f;

        for (int kk = 0; kk < 128; kk += 4) {
            float4 q4[4], kf[4];
#pragma unroll
            for (int i = 0; i < 4; i++)
                q4[i] = *(const float4*)&Qs[(ty * 4 + i) * 132 + kk];
#pragma unroll
            for (int u = 0; u < 4; u++)
                kf[u] = *(const float4*)&KsT[(kk + u) * 68 + tx * 4];
#pragma unroll
            for (int i = 0; i < 4; i++) {
                s[i][0] += q4[i].x * kf[0].x + q4[i].y * kf[1].x + q4[i].z * kf[2].x + q4[i].w * kf[3].x;
                s[i][1] += q4[i].x * kf[0].y + q4[i].y * kf[1].y + q4[i].z * kf[2].y + q4[i].w * kf[3].y;
                s[i][2] += q4[i].x * kf[0].z + q4[i].y * kf[1].z + q4[i].z * kf[2].z + q4[i].w * kf[3].z;
                s[i][3] += q4[i].x * kf[0].w + q4[i].y * kf[1].w + q4[i].z * kf[2].w + q4[i].w * kf[3].w;
            }
        }

#pragma unroll
        for (int i = 0; i < 4; i++)
#pragma unroll
            for (int j = 0; j < 4; j++) s[i][j] *= sc;

        if (kt == qt) {
#pragma unroll
            for (int i = 0; i < 4; i++)
#pragma unroll
                for (int j = 0; j < 4; j++)
                    if (k0 + tx * 4 + j > q0 + ty * 4 + i) s[i][j] = -1e30f;
        }

        // ---- online softmax per row ----
#pragma unroll
        for (int i = 0; i < 4; i++) {
            float mx = fmaxf(fmaxf(s[i][0], s[i][1]), fmaxf(s[i][2], s[i][3]));
#pragma unroll
            for (int off = 1; off <= 8; off <<= 1)
                mx = fmaxf(mx, __shfl_xor_sync(0xffffffffu, mx, off));
            float mnew = fmaxf(mrow[i], mx);
            float p0 = __expf(s[i][0] - mnew);
            float p1 = __expf(s[i][1] - mnew);
            float p2 = __expf(s[i][2] - mnew);
            float p3 = __expf(s[i][3] - mnew);
            float rs = p0 + p1 + p2 + p3;
#pragma unroll
            for (int off = 1; off <= 8; off <<= 1)
                rs += __shfl_xor_sync(0xffffffffu, rs, off);
            float corr = __expf(mrow[i] - mnew);
            lrow[i] = lrow[i] * corr + rs;
            mrow[i] = mnew;
#pragma unroll
            for (int j = 0; j < 8; j++) o[i][j] *= corr;
            *(float4*)&Ps[(ty * 4 + i) * 64 + tx * 4] = make_float4(p0, p1, p2, p3);
        }
        __syncthreads();

        // ---- O += P V (4x8 microtile) ----
        for (int kk = 0; kk < 64; kk++) {
            float4 v0 = *(const float4*)&Vs[kk * 132 + tx * 8];
            float4 v1 = *(const float4*)&Vs[kk * 132 + tx * 8 + 4];
#pragma unroll
            for (int i = 0; i < 4; i++) {
                float p = Ps[(ty * 4 + i) * 64 + kk];
                o[i][0] += p * v0.x; o[i][1] += p * v0.y;
                o[i][2] += p * v0.z; o[i][3] += p * v0.w;
                o[i][4] += p * v1.x; o[i][5] += p * v1.y;
                o[i][6] += p * v1.z; o[i][7] += p * v1.w;
            }
        }
    }

    // Epilogue: normalize and write y[b, t, h*128 + d]
#pragma unroll
    for (int i = 0; i < 4; i++) {
        float inv = 1.f / lrow[i];
        int r = q0 + ty * 4 + i;
        float* yp = y + (size_t)(b * T_ + r) * C_ + h * 128 + tx * 8;
        *(float4*)(yp)     = make_float4(o[i][0] * inv, o[i][1] * inv, o[i][2] * inv, o[i][3] * inv);
        *(float4*)(yp + 4) = make_float4(o[i][4] * inv, o[i][5] * inv, o[i][6] * inv, o[i][7] * inv);
    }
}

// ---------------------------------------------------------------------------
// Launch
// ---------------------------------------------------------------------------
extern "C" void kernel_launch(void* const* d_in, const int* in_sizes, int n_in,
                              void* d_out, int out_size)
{
    const float* x     = (const float*)d_in[0];
    const float* cosb  = (const float*)d_in[1];
    const float* sinb  = (const float*)d_in[2];
    const float* Wqkv  = (const float*)d_in[3];
    const float* Wproj = (const float*)d_in[4];
    float* out = (float*)d_out;

    float* qkv = nullptr;
    float* yb  = nullptr;
    cudaGetSymbolAddress((void**)&qkv, g_qkv);
    cudaGetSymbolAddress((void**)&yb, g_y);

    cudaFuncSetAttribute(attn_kernel,
                         cudaFuncAttributeMaxDynamicSharedMemorySize,
                         ATT_SMEM_BYTES);

    // 1) QKV = x @ W_qkv^T
    sgemm_abt<<<dim3(NQKV_ / 128, M_ / 128), 256>>>(x, Wqkv, qkv, M_, NQKV_, C_);

    // 2) RoPE in place on q + k slots
    {
        int total = M_ * NG_ * 5 * 64;
        rope_kernel<<<(total + 255) / 256, 256>>>(qkv, cosb, sinb);
    }

    // 3) causal GQA attention -> y [B*T, C]
    attn_kernel<<<dim3(T_ / 64, B_ * NH_), 256, ATT_SMEM_BYTES>>>(qkv, yb);

    // 4) out = y @ W_proj^T
    sgemm_abt<<<dim3(C_ / 128, M_ / 128), 256>>>(yb, Wproj, out, M_, C_, C_);
}

// round 3
// speedup vs baseline: 1.8300x; 1.8300x over previous
#include <cuda_runtime.h>
#include <cuda_bf16.h>
#include <math.h>
#include <stdint.h>

// Problem constants
#define B_    2
#define T_    2048
#define C_    4096
#define NH_   32
#define NG_   8
#define HS_   128
#define M_    (B_ * T_)                 // 4096 rows
#define NQKV_ ((NH_ + 2 * NG_) * HS_)   // 6144

// Scratch (no cudaMalloc allowed)
__device__ float g_qkv[(size_t)M_ * NQKV_];            // ~100.7 MB
__device__ float g_y[(size_t)M_ * C_];                 // ~67 MB
__device__ __nv_bfloat16 g_a_hi[(size_t)M_ * C_];      // 32 MB
__device__ __nv_bfloat16 g_a_lo[(size_t)M_ * C_];      // 32 MB
__device__ __nv_bfloat16 g_b_hi[(size_t)NQKV_ * C_];   // 48 MB
__device__ __nv_bfloat16 g_b_lo[(size_t)NQKV_ * C_];   // 48 MB

// ===========================================================================
// PTX helpers (sm_100 base target: mma.sync / ldmatrix / cp.async only)
// ===========================================================================
__device__ __forceinline__ uint32_t smem_to_u32(const void* p) {
    uint32_t a;
    asm("{ .reg .u64 t; cvta.to.shared.u64 t, %1; cvt.u32.u64 %0, t; }"
        : "=r"(a) : "l"(p));
    return a;
}
__device__ __forceinline__ void cp_async16(uint32_t dst, const void* src) {
    asm volatile("cp.async.cg.shared.global [%0], [%1], 16;" :: "r"(dst), "l"(src));
}
__device__ __forceinline__ void cp_commit() {
    asm volatile("cp.async.commit_group;");
}
template <int N> __device__ __forceinline__ void cp_wait() {
    asm volatile("cp.async.wait_group %0;" :: "n"(N));
}
__device__ __forceinline__ void ldsm4(uint32_t* r, uint32_t addr) {
    asm volatile("ldmatrix.sync.aligned.m8n8.x4.shared.b16 {%0,%1,%2,%3}, [%4];"
        : "=r"(r[0]), "=r"(r[1]), "=r"(r[2]), "=r"(r[3]) : "r"(addr));
}
__device__ __forceinline__ void mma_bf16(float* d, const uint32_t* a,
                                         uint32_t b0, uint32_t b1) {
    asm volatile(
        "mma.sync.aligned.m16n8k16.row.col.f32.bf16.bf16.f32 "
        "{%0,%1,%2,%3}, {%4,%5,%6,%7}, {%8,%9}, {%0,%1,%2,%3};"
        : "+f"(d[0]), "+f"(d[1]), "+f"(d[2]), "+f"(d[3])
        : "r"(a[0]), "r"(a[1]), "r"(a[2]), "r"(a[3]), "r"(b0), "r"(b1));
}

// ===========================================================================
// HMMA GEMM: C[M,N] = Ahi@Bhi^T + Ahi@Blo^T + Alo@Bhi^T  (bf16x3 -> fp32)
// A,B row-major with K contiguous. Tile 128x128x32, 256 threads (8 warps 4x2),
// warp tile 32x64, cp.async double buffer, ldmatrix fragments (pad-40 rows).
// ===========================================================================
#define BM 128
#define BN 128
#define BK 32
#define PADK 40
#define MAT_ELEMS (128 * PADK)          // 5120 bf16
#define STAGE_ELEMS (4 * MAT_ELEMS)     // 20480 bf16 (40960 B)
#define GEMM_SMEM (2 * STAGE_ELEMS * 2) // 81920 B

__global__ __launch_bounds__(256) void hmma_gemm(
    const __nv_bfloat16* __restrict__ Ahi, const __nv_bfloat16* __restrict__ Alo,
    const __nv_bfloat16* __restrict__ Bhi, const __nv_bfloat16* __restrict__ Blo,
    float* __restrict__ C, int Ntot, int K)
{
    extern __shared__ __nv_bfloat16 smb[];
    const int tid  = threadIdx.x;
    const int wid  = tid >> 5;
    const int lane = tid & 31;
    const int wm   = wid & 3;     // warp M: 0..3 (rows wm*32..+31)
    const int wn   = wid >> 2;    // warp N: 0..1 (cols wn*64..+63)
    const int m0   = blockIdx.x * BM;
    const int n0   = blockIdx.y * BN;
    const uint32_t sbase = smem_to_u32(smb);

    float acc[2][8][4];
#pragma unroll
    for (int i = 0; i < 2; i++)
#pragma unroll
        for (int j = 0; j < 8; j++)
#pragma unroll
            for (int v = 0; v < 4; v++) acc[i][j][v] = 0.f;

    // stage loader: 4 matrices x 128 rows x 4 chunks(16B) = 2048 cp.async
    auto issue_stage = [&](int s, int k0) {
        uint32_t dstb = sbase + s * (STAGE_ELEMS * 2);
#pragma unroll
        for (int i = 0; i < 8; i++) {
            int idx = i * 256 + tid;
            int mat = idx >> 9;          // 0=Ahi 1=Alo 2=Bhi 3=Blo
            int rem = idx & 511;
            int row = rem >> 2;
            int ch  = rem & 3;
            int grow = (mat < 2) ? (m0 + row) : (n0 + row);
            const __nv_bfloat16* base =
                (mat == 0) ? Ahi : (mat == 1) ? Alo : (mat == 2) ? Bhi : Blo;
            const __nv_bfloat16* src = base + (size_t)grow * K + k0 + ch * 8;
            uint32_t d = dstb + (uint32_t)(mat * MAT_ELEMS + row * PADK + ch * 8) * 2;
            cp_async16(d, src);
        }
    };

    issue_stage(0, 0);
    cp_commit();

    const int nk = K / BK;
    for (int it = 0; it < nk; it++) {
        const int s = it & 1;
        if (it + 1 < nk) {
            issue_stage(s ^ 1, (it + 1) * BK);
            cp_commit();
            cp_wait<1>();
        } else {
            cp_wait<0>();
        }
        __syncthreads();

        const uint32_t stb = sbase + s * (STAGE_ELEMS * 2);
#pragma unroll
        for (int kk = 0; kk < 2; kk++) {
            uint32_t ah[2][4], al[2][4], bh[4][4], bl[4][4];
#pragma unroll
            for (int mt = 0; mt < 2; mt++) {
                int row = wm * 32 + mt * 16 + (lane & 15);
                int kof = kk * 16 + (lane >> 4) * 8;
                uint32_t a = stb + (uint32_t)(row * PADK + kof) * 2;
                ldsm4(ah[mt], a);
                ldsm4(al[mt], a + MAT_ELEMS * 2);
            }
#pragma unroll
            for (int nt = 0; nt < 4; nt++) {
                int n   = wn * 64 + nt * 16 + (lane & 7) + ((lane >> 4) << 3);
                int kof = kk * 16 + ((lane >> 3) & 1) * 8;
                uint32_t a = stb + (uint32_t)(2 * MAT_ELEMS + n * PADK + kof) * 2;
                ldsm4(bh[nt], a);
                ldsm4(bl[nt], a + MAT_ELEMS * 2);
            }
#pragma unroll
            for (int mt = 0; mt < 2; mt++)
#pragma unroll
                for (int n8 = 0; n8 < 8; n8++) {
                    uint32_t b0h = bh[n8 >> 1][(n8 & 1) * 2];
                    uint32_t b1h = bh[n8 >> 1][(n8 & 1) * 2 + 1];
                    uint32_t b0l = bl[n8 >> 1][(n8 & 1) * 2];
                    uint32_t b1l = bl[n8 >> 1][(n8 & 1) * 2 + 1];
                    mma_bf16(acc[mt][n8], ah[mt], b0h, b1h);
                    mma_bf16(acc[mt][n8], ah[mt], b0l, b1l);
                    mma_bf16(acc[mt][n8], al[mt], b0h, b1h);
                }
        }
        __syncthreads();
    }

    // Epilogue: fragment layout -> fp32 stores (float2, coalesced per quad)
#pragma unroll
    for (int mt = 0; mt < 2; mt++) {
        int r0 = m0 + wm * 32 + mt * 16 + (lane >> 2);
#pragma unroll
        for (int n8 = 0; n8 < 8; n8++) {
            int col = n0 + wn * 64 + n8 * 8 + (lane & 3) * 2;
            *(float2*)(C + (size_t)r0 * Ntot + col) =
                make_float2(acc[mt][n8][0], acc[mt][n8][1]);
            *(float2*)(C + (size_t)(r0 + 8) * Ntot + col) =
                make_float2(acc[mt][n8][2], acc[mt][n8][3]);
        }
    }
}

// ===========================================================================
// fp32 -> bf16 hi/lo split (vectorized by 4)
// ===========================================================================
__global__ void split_bf16_kernel(const float* __restrict__ in,
                                  __nv_bfloat16* __restrict__ hi,
                                  __nv_bfloat16* __restrict__ lo, int n4)
{
    int i = blockIdx.x * blockDim.x + threadIdx.x;
    if (i >= n4) return;
    float4 v = *(const float4*)(in + (size_t)i * 4);
    __nv_bfloat16 h0 = __float2bfloat16(v.x);
    __nv_bfloat16 h1 = __float2bfloat16(v.y);
    __nv_bfloat16 h2 = __float2bfloat16(v.z);
    __nv_bfloat16 h3 = __float2bfloat16(v.w);
    __nv_bfloat16 l0 = __float2bfloat16(v.x - __bfloat162float(h0));
    __nv_bfloat16 l1 = __float2bfloat16(v.y - __bfloat162float(h1));
    __nv_bfloat16 l2 = __float2bfloat16(v.z - __bfloat162float(h2));
    __nv_bfloat16 l3 = __float2bfloat16(v.w - __bfloat162float(h3));
    __nv_bfloat162 hp0 = __nv_bfloat162(h0, h1), hp1 = __nv_bfloat162(h2, h3);
    __nv_bfloat162 lp0 = __nv_bfloat162(l0, l1), lp1 = __nv_bfloat162(l2, l3);
    *(uint2*)(hi + (size_t)i * 4) = make_uint2(*(uint32_t*)&hp0, *(uint32_t*)&hp1);
    *(uint2*)(lo + (size_t)i * 4) = make_uint2(*(uint32_t*)&lp0, *(uint32_t*)&lp1);
}

// ===========================================================================
// In-place RoPE on q (slots 0..3) and k (slot 4) inside g_qkv.
// ===========================================================================
__global__ void rope_kernel(float* __restrict__ qkv,
                            const float* __restrict__ cs,
                            const float* __restrict__ sn)
{
    int idx = blockIdx.x * blockDim.x + threadIdx.x;
    const int total = M_ * NG_ * 5 * 64;
    if (idx >= total) return;

    int d = idx & 63;
    int r = idx >> 6;
    int slot = r % 5; r /= 5;
    int g    = r % NG_; r /= NG_;
    int t = r & (T_ - 1);

    float* p = qkv + (size_t)r * NQKV_ + g * (6 * HS_) + slot * HS_;
    float x1 = p[d];
    float x2 = p[d + 64];
    float c1 = cs[t * HS_ + d],      s1 = sn[t * HS_ + d];
    float c2 = cs[t * HS_ + d + 64], s2 = sn[t * HS_ + d + 64];
    p[d]      = x1 * c1 - x2 * s1;
    p[d + 64] = x2 * c2 + x1 * s2;
}

// ===========================================================================
// FP32 causal flash attention (unchanged, known-good from R1).
// ===========================================================================
#define ATT_SMEM_BYTES ((64 * 132 + 128 * 68 + 64 * 132 + 64 * 64) * 4)

__global__ __launch_bounds__(256) void attn_kernel(
    const float* __restrict__ qkv, float* __restrict__ y)
{
    extern __shared__ float sm[];
    float* Qs  = sm;
    float* KsT = Qs + 64 * 132;
    float* Vs  = KsT + 128 * 68;
    float* Ps  = Vs + 64 * 132;

    const int tid = threadIdx.x;
    const int ty  = tid >> 4;
    const int tx  = tid & 15;
    const int qt  = blockIdx.x;
    const int bh  = blockIdx.y;
    const int b   = bh >> 5;
    const int h   = bh & 31;
    const int g   = h >> 2;
    const int qi  = h & 3;

    const float* qb = qkv + (size_t)b * T_ * NQKV_ + g * 768 + qi * 128;
    const float* kb = qkv + (size_t)b * T_ * NQKV_ + g * 768 + 512;
    const float* vb = kb + 128;
    const int q0 = qt * 64;

    for (int i = tid; i < 64 * 32; i += 256) {
        int r  = i >> 5;
        int c4 = (i & 31) << 2;
        *(float4*)&Qs[r * 132 + c4] =
            *(const float4*)(qb + (size_t)(q0 + r) * NQKV_ + c4);
    }

    float o[4][8];
    float mrow[4], lrow[4];
#pragma unroll
    for (int i = 0; i < 4; i++) {
        mrow[i] = -1e30f;
        lrow[i] = 0.f;
#pragma unroll
        for (int j = 0; j < 8; j++) o[i][j] = 0.f;
    }

    const float sc = 0.08838834764831845f;

    for (int kt = 0; kt <= qt; kt++) {
        const int k0 = kt * 64;
        __syncthreads();

        for (int i = tid; i < 64 * 32; i += 256) {
            int r  = i & 63;
            int c4 = (i >> 6) << 2;
            float4 kv = *(const float4*)(kb + (size_t)(k0 + r) * NQKV_ + c4);
            KsT[(c4 + 0) * 68 + r] = kv.x;
            KsT[(c4 + 1) * 68 + r] = kv.y;
            KsT[(c4 + 2) * 68 + r] = kv.z;
            KsT[(c4 + 3) * 68 + r] = kv.w;
        }
        for (int i = tid; i < 64 * 32; i += 256) {
            int r  = i >> 5;
            int c4 = (i & 31) << 2;
            *(float4*)&Vs[r * 132 + c4] =
                *(const float4*)(vb + (size_t)(k0 + r) * NQKV_ + c4);
        }
        __syncthreads();

        float s[4][4];
#pragma unroll
        for (int i = 0; i < 4; i++)
#pragma unroll
            for (int j = 0; j < 4; j++) s[i][j] = 0.f;

        for (int kk = 0; kk < 128; kk += 4) {
            float4 q4[4], kf[4];
#pragma unroll
            for (int i = 0; i < 4; i++)
                q4[i] = *(const float4*)&Qs[(ty * 4 + i) * 132 + kk];
#pragma unroll
            for (int u = 0; u < 4; u++)
                kf[u] = *(const float4*)&KsT[(kk + u) * 68 + tx * 4];
#pragma unroll
            for (int i = 0; i < 4; i++) {
                s[i][0] += q4[i].x * kf[0].x + q4[i].y * kf[1].x + q4[i].z * kf[2].x + q4[i].w * kf[3].x;
                s[i][1] += q4[i].x * kf[0].y + q4[i].y * kf[1].y + q4[i].z * kf[2].y + q4[i].w * kf[3].y;
                s[i][2] += q4[i].x * kf[0].z + q4[i].y * kf[1].z + q4[i].z * kf[2].z + q4[i].w * kf[3].z;
                s[i][3] += q4[i].x * kf[0].w + q4[i].y * kf[1].w + q4[i].z * kf[2].w + q4[i].w * kf[3].w;
            }
        }

#pragma unroll
        for (int i = 0; i < 4; i++)
#pragma unroll
            for (int j = 0; j < 4; j++) s[i][j] *= sc;

        if (kt == qt) {
#pragma unroll
            for (int i = 0; i < 4; i++)
#pragma unroll
                for (int j = 0; j < 4; j++)
                    if (k0 + tx * 4 + j > q0 + ty * 4 + i) s[i][j] = -1e30f;
        }

#pragma unroll
        for (int i = 0; i < 4; i++) {
            float mx = fmaxf(fmaxf(s[i][0], s[i][1]), fmaxf(s[i][2], s[i][3]));
#pragma unroll
            for (int off = 1; off <= 8; off <<= 1)
                mx = fmaxf(mx, __shfl_xor_sync(0xffffffffu, mx, off));
            float mnew = fmaxf(mrow[i], mx);
            float p0 = __expf(s[i][0] - mnew);
            float p1 = __expf(s[i][1] - mnew);
            float p2 = __expf(s[i][2] - mnew);
            float p3 = __expf(s[i][3] - mnew);
            float rs = p0 + p1 + p2 + p3;
#pragma unroll
            for (int off = 1; off <= 8; off <<= 1)
                rs += __shfl_xor_sync(0xffffffffu, rs, off);
            float corr = __expf(mrow[i] - mnew);
            lrow[i] = lrow[i] * corr + rs;
            mrow[i] = mnew;
#pragma unroll
            for (int j = 0; j < 8; j++) o[i][j] *= corr;
            *(float4*)&Ps[(ty * 4 + i) * 64 + tx * 4] = make_float4(p0, p1, p2, p3);
        }
        __syncthreads();

        for (int kk = 0; kk < 64; kk++) {
            float4 v0 = *(const float4*)&Vs[kk * 132 + tx * 8];
            float4 v1 = *(const float4*)&Vs[kk * 132 + tx * 8 + 4];
#pragma unroll
            for (int i = 0; i < 4; i++) {
                float p = Ps[(ty * 4 + i) * 64 + kk];
                o[i][0] += p * v0.x; o[i][1] += p * v0.y;
                o[i][2] += p * v0.z; o[i][3] += p * v0.w;
                o[i][4] += p * v1.x; o[i][5] += p * v1.y;
                o[i][6] += p * v1.z; o[i][7] += p * v1.w;
            }
        }
    }

#pragma unroll
    for (int i = 0; i < 4; i++) {
        float inv = 1.f / lrow[i];
        int r = q0 + ty * 4 + i;
        float* yp = y + (size_t)(b * T_ + r) * C_ + h * 128 + tx * 8;
        *(float4*)(yp)     = make_float4(o[i][0] * inv, o[i][1] * inv, o[i][2] * inv, o[i][3] * inv);
        *(float4*)(yp + 4) = make_float4(o[i][4] * inv, o[i][5] * inv, o[i][6] * inv, o[i][7] * inv);
    }
}

// ===========================================================================
// Launch
// ===========================================================================
extern "C" void kernel_launch(void* const* d_in, const int* in_sizes, int n_in,
                              void* d_out, int out_size)
{
    const float* x     = (const float*)d_in[0];
    const float* cosb  = (const float*)d_in[1];
    const float* sinb  = (const float*)d_in[2];
    const float* Wqkv  = (const float*)d_in[3];
    const float* Wproj = (const float*)d_in[4];
    float* out = (float*)d_out;

    float *qkv = nullptr, *yb = nullptr;
    __nv_bfloat16 *ahi, *alo, *bhi, *blo;
    cudaGetSymbolAddress((void**)&qkv, g_qkv);
    cudaGetSymbolAddress((void**)&yb,  g_y);
    cudaGetSymbolAddress((void**)&ahi, g_a_hi);
    cudaGetSymbolAddress((void**)&alo, g_a_lo);
    cudaGetSymbolAddress((void**)&bhi, g_b_hi);
    cudaGetSymbolAddress((void**)&blo, g_b_lo);

    cudaFuncSetAttribute(attn_kernel, cudaFuncAttributeMaxDynamicSharedMemorySize,
                         ATT_SMEM_BYTES);
    cudaFuncSetAttribute(hmma_gemm, cudaFuncAttributeMaxDynamicSharedMemorySize,
                         GEMM_SMEM);

    // ---- GEMM 1: qkv = x @ Wqkv^T  (M=4096, N=6144, K=4096) ----
    {
        int n4a = M_ * C_ / 4, n4b = NQKV_ * C_ / 4;
        split_bf16_kernel<<<(n4a + 255) / 256, 256>>>(x, ahi, alo, n4a);
        split_bf16_kernel<<<(n4b + 255) / 256, 256>>>(Wqkv, bhi, blo, n4b);
        hmma_gemm<<<dim3(M_ / BM, NQKV_ / BN), 256, GEMM_SMEM>>>(
            ahi, alo, bhi, blo, qkv, NQKV_, C_);
    }

    // ---- RoPE in place ----
    {
        int total = M_ * NG_ * 5 * 64;
        rope_kernel<<<(total + 255) / 256, 256>>>(qkv, cosb, sinb);
    }

    // ---- Attention -> g_y ----
    attn_kernel<<<dim3(T_ / 64, B_ * NH_), 256, ATT_SMEM_BYTES>>>(qkv, yb);

    // ---- GEMM 2: out = y @ Wproj^T  (M=4096, N=4096, K=4096) ----
    {
        int n4a = M_ * C_ / 4, n4b = C_ * C_ / 4;
        split_bf16_kernel<<<(n4a + 255) / 256, 256>>>(yb, ahi, alo, n4a);
        split_bf16_kernel<<<(n4b + 255) / 256, 256>>>(Wproj, bhi, blo, n4b);
        hmma_gemm<<<dim3(M_ / BM, C_ / BN), 256, GEMM_SMEM>>>(
            ahi, alo, bhi, blo, out, C_, C_);
    }
}

// round 4
// speedup vs baseline: 2.7664x; 1.5117x over previous
#include <cuda_runtime.h>
#include <cuda_bf16.h>
#include <math.h>
#include <stdint.h>

// Problem constants
#define B_    2
#define T_    2048
#define C_    4096
#define NH_   32
#define NG_   8
#define HS_   128
#define M_    (B_ * T_)                 // 4096 rows
#define NQKV_ ((NH_ + 2 * NG_) * HS_)   // 6144

// Scratch (no cudaMalloc allowed)
__device__ float g_qkv[(size_t)M_ * NQKV_];               // 100.7 MB fp32 qkv
__device__ __nv_bfloat16 g_att_hi[(size_t)M_ * NQKV_];    // 50 MB roped q,k hi + v hi
__device__ __nv_bfloat16 g_att_lo[(size_t)M_ * NQKV_];    // 50 MB (v lo slots used)
__device__ __nv_bfloat16 g_a_hi[(size_t)M_ * C_];         // 32 MB (x hi / y hi)
__device__ __nv_bfloat16 g_a_lo[(size_t)M_ * C_];         // 32 MB
__device__ __nv_bfloat16 g_b_hi[(size_t)NQKV_ * C_];      // 48 MB (W hi)
__device__ __nv_bfloat16 g_b_lo[(size_t)NQKV_ * C_];      // 48 MB

// ===========================================================================
// PTX helpers (sm_100 base target: mma.sync / ldmatrix / cp.async only)
// ===========================================================================
__device__ __forceinline__ uint32_t smem_to_u32(const void* p) {
    uint32_t a;
    asm("{ .reg .u64 t; cvta.to.shared.u64 t, %1; cvt.u32.u64 %0, t; }"
        : "=r"(a) : "l"(p));
    return a;
}
__device__ __forceinline__ void cp_async16(uint32_t dst, const void* src) {
    asm volatile("cp.async.cg.shared.global [%0], [%1], 16;" :: "r"(dst), "l"(src));
}
__device__ __forceinline__ void cp_commit() {
    asm volatile("cp.async.commit_group;");
}
template <int N> __device__ __forceinline__ void cp_wait() {
    asm volatile("cp.async.wait_group %0;" :: "n"(N));
}
__device__ __forceinline__ void ldsm4(uint32_t* r, uint32_t addr) {
    asm volatile("ldmatrix.sync.aligned.m8n8.x4.shared.b16 {%0,%1,%2,%3}, [%4];"
        : "=r"(r[0]), "=r"(r[1]), "=r"(r[2]), "=r"(r[3]) : "r"(addr));
}
__device__ __forceinline__ void ldsm4t(uint32_t* r, uint32_t addr) {
    asm volatile("ldmatrix.sync.aligned.m8n8.x4.trans.shared.b16 {%0,%1,%2,%3}, [%4];"
        : "=r"(r[0]), "=r"(r[1]), "=r"(r[2]), "=r"(r[3]) : "r"(addr));
}
__device__ __forceinline__ void mma_bf16(float* d, const uint32_t* a,
                                         uint32_t b0, uint32_t b1) {
    asm volatile(
        "mma.sync.aligned.m16n8k16.row.col.f32.bf16.bf16.f32 "
        "{%0,%1,%2,%3}, {%4,%5,%6,%7}, {%8,%9}, {%0,%1,%2,%3};"
        : "+f"(d[0]), "+f"(d[1]), "+f"(d[2]), "+f"(d[3])
        : "r"(a[0]), "r"(a[1]), "r"(a[2]), "r"(a[3]), "r"(b0), "r"(b1));
}
__device__ __forceinline__ uint32_t pack_bf16(float lo_val, float hi_val) {
    __nv_bfloat162 p = __nv_bfloat162(__float2bfloat16(lo_val), __float2bfloat16(hi_val));
    return *(uint32_t*)&p;
}

// ===========================================================================
// HMMA GEMM: C = Ahi@Bhi^T + Ahi@Blo^T + Alo@Bhi^T. 128x128x32 tiles,
// 256 threads (8 warps 4x2), 3-stage cp.async pipeline, pad-40 smem rows.
// ===========================================================================
#define BM 128
#define BN 128
#define BK 32
#define PADK 40
#define MAT_ELEMS (128 * PADK)            // 5120 bf16
#define STAGE_ELEMS (4 * MAT_ELEMS)       // 20480 bf16
#define GEMM_SMEM (3 * STAGE_ELEMS * 2)   // 122880 B

__global__ __launch_bounds__(256) void hmma_gemm(
    const __nv_bfloat16* __restrict__ Ahi, const __nv_bfloat16* __restrict__ Alo,
    const __nv_bfloat16* __restrict__ Bhi, const __nv_bfloat16* __restrict__ Blo,
    float* __restrict__ C, int Ntot, int K)
{
    extern __shared__ __nv_bfloat16 smb[];
    const int tid  = threadIdx.x;
    const int wid  = tid >> 5;
    const int lane = tid & 31;
    const int wm   = wid & 3;
    const int wn   = wid >> 2;
    const int m0   = blockIdx.x * BM;
    const int n0   = blockIdx.y * BN;
    const uint32_t sbase = smem_to_u32(smb);

    float acc[2][8][4];
#pragma unroll
    for (int i = 0; i < 2; i++)
#pragma unroll
        for (int j = 0; j < 8; j++)
#pragma unroll
            for (int v = 0; v < 4; v++) acc[i][j][v] = 0.f;

    auto issue_stage = [&](int s, int k0) {
        uint32_t dstb = sbase + s * (STAGE_ELEMS * 2);
#pragma unroll
        for (int i = 0; i < 8; i++) {
            int idx = i * 256 + tid;
            int mat = idx >> 9;
            int rem = idx & 511;
            int row = rem >> 2;
            int ch  = rem & 3;
            int grow = (mat < 2) ? (m0 + row) : (n0 + row);
            const __nv_bfloat16* base =
                (mat == 0) ? Ahi : (mat == 1) ? Alo : (mat == 2) ? Bhi : Blo;
            const __nv_bfloat16* src = base + (size_t)grow * K + k0 + ch * 8;
            uint32_t d = dstb + (uint32_t)(mat * MAT_ELEMS + row * PADK + ch * 8) * 2;
            cp_async16(d, src);
        }
    };

    issue_stage(0, 0);
    cp_commit();
    issue_stage(1, BK);
    cp_commit();

    const int nk = K / BK;
    int s = 0;
    for (int it = 0; it < nk; it++) {
        if (it + 2 < nk) {
            int sn = (s + 2) % 3;
            issue_stage(sn, (it + 2) * BK);
            cp_commit();
            cp_wait<2>();
        } else if (it + 1 < nk) {
            cp_wait<1>();
        } else {
            cp_wait<0>();
        }
        __syncthreads();

        const uint32_t stb = sbase + s * (STAGE_ELEMS * 2);
#pragma unroll
        for (int kk = 0; kk < 2; kk++) {
            uint32_t ah[2][4], al[2][4], bh[4][4], bl[4][4];
#pragma unroll
            for (int mt = 0; mt < 2; mt++) {
                int row = wm * 32 + mt * 16 + (lane & 15);
                int kof = kk * 16 + (lane >> 4) * 8;
                uint32_t a = stb + (uint32_t)(row * PADK + kof) * 2;
                ldsm4(ah[mt], a);
                ldsm4(al[mt], a + MAT_ELEMS * 2);
            }
#pragma unroll
            for (int nt = 0; nt < 4; nt++) {
                int n   = wn * 64 + nt * 16 + (lane & 7) + ((lane >> 4) << 3);
                int kof = kk * 16 + ((lane >> 3) & 1) * 8;
                uint32_t a = stb + (uint32_t)(2 * MAT_ELEMS + n * PADK + kof) * 2;
                ldsm4(bh[nt], a);
                ldsm4(bl[nt], a + MAT_ELEMS * 2);
            }
#pragma unroll
            for (int mt = 0; mt < 2; mt++)
#pragma unroll
                for (int n8 = 0; n8 < 8; n8++) {
                    uint32_t b0h = bh[n8 >> 1][(n8 & 1) * 2];
                    uint32_t b1h = bh[n8 >> 1][(n8 & 1) * 2 + 1];
                    uint32_t b0l = bl[n8 >> 1][(n8 & 1) * 2];
                    uint32_t b1l = bl[n8 >> 1][(n8 & 1) * 2 + 1];
                    mma_bf16(acc[mt][n8], ah[mt], b0h, b1h);
                    mma_bf16(acc[mt][n8], ah[mt], b0l, b1l);
                    mma_bf16(acc[mt][n8], al[mt], b0h, b1h);
                }
        }
        __syncthreads();
        s = (s + 1) % 3;
    }

#pragma unroll
    for (int mt = 0; mt < 2; mt++) {
        int r0 = m0 + wm * 32 + mt * 16 + (lane >> 2);
#pragma unroll
        for (int n8 = 0; n8 < 8; n8++) {
            int col = n0 + wn * 64 + n8 * 8 + (lane & 3) * 2;
            *(float2*)(C + (size_t)r0 * Ntot + col) =
                make_float2(acc[mt][n8][0], acc[mt][n8][1]);
            *(float2*)(C + (size_t)(r0 + 8) * Ntot + col) =
                make_float2(acc[mt][n8][2], acc[mt][n8][3]);
        }
    }
}

// ===========================================================================
// fp32 -> bf16 hi/lo split (vectorized by 4)
// ===========================================================================
__global__ void split_bf16_kernel(const float* __restrict__ in,
                                  __nv_bfloat16* __restrict__ hi,
                                  __nv_bfloat16* __restrict__ lo, int n4)
{
    int i = blockIdx.x * blockDim.x + threadIdx.x;
    if (i >= n4) return;
    float4 v = *(const float4*)(in + (size_t)i * 4);
    __nv_bfloat16 h0 = __float2bfloat16(v.x);
    __nv_bfloat16 h1 = __float2bfloat16(v.y);
    __nv_bfloat16 h2 = __float2bfloat16(v.z);
    __nv_bfloat16 h3 = __float2bfloat16(v.w);
    __nv_bfloat16 l0 = __float2bfloat16(v.x - __bfloat162float(h0));
    __nv_bfloat16 l1 = __float2bfloat16(v.y - __bfloat162float(h1));
    __nv_bfloat16 l2 = __float2bfloat16(v.z - __bfloat162float(h2));
    __nv_bfloat16 l3 = __float2bfloat16(v.w - __bfloat162float(h3));
    __nv_bfloat162 hp0 = __nv_bfloat162(h0, h1), hp1 = __nv_bfloat162(h2, h3);
    __nv_bfloat162 lp0 = __nv_bfloat162(l0, l1), lp1 = __nv_bfloat162(l2, l3);
    *(uint2*)(hi + (size_t)i * 4) = make_uint2(*(uint32_t*)&hp0, *(uint32_t*)&hp1);
    *(uint2*)(lo + (size_t)i * 4) = make_uint2(*(uint32_t*)&lp0, *(uint32_t*)&lp1);
}

// ===========================================================================
// RoPE + bf16 conversion: q,k slots roped -> att_hi (bf16);
// v slot hi/lo split -> att_hi/att_lo. One thread per (d, d+64) pair.
// ===========================================================================
__global__ void rope_split_kernel(const float* __restrict__ qkv,
                                  const float* __restrict__ cs,
                                  const float* __restrict__ sn,
                                  __nv_bfloat16* __restrict__ ah,
                                  __nv_bfloat16* __restrict__ al)
{
    int idx = blockIdx.x * blockDim.x + threadIdx.x;
    const int total = M_ * NG_ * 6 * 64;
    if (idx >= total) return;

    int d = idx & 63;
    int r = idx >> 6;
    int slot = r % 6; r /= 6;
    int g    = r % NG_; r /= NG_;
    int t = r & (T_ - 1);

    size_t off = (size_t)r * NQKV_ + g * 768 + slot * 128;
    const float* p = qkv + off;
    float x1 = p[d];
    float x2 = p[d + 64];

    if (slot < 5) {
        float c1 = cs[t * HS_ + d],      s1 = sn[t * HS_ + d];
        float c2 = cs[t * HS_ + d + 64], s2 = sn[t * HS_ + d + 64];
        ah[off + d]      = __float2bfloat16(x1 * c1 - x2 * s1);
        ah[off + d + 64] = __float2bfloat16(x2 * c2 + x1 * s2);
    } else {
        __nv_bfloat16 h1 = __float2bfloat16(x1);
        __nv_bfloat16 h2 = __float2bfloat16(x2);
        ah[off + d]      = h1;
        ah[off + d + 64] = h2;
        al[off + d]      = __float2bfloat16(x1 - __bfloat162float(h1));
        al[off + d + 64] = __float2bfloat16(x2 - __bfloat162float(h2));
    }
}

// ===========================================================================
// HMMA causal flash attention. Block = 128 thr (4 warps), 64 q-rows/block,
// 64-key tiles, double-buffered cp.async. QK bf16; PV split (Phi*Vhi +
// Phi*Vlo + Plo*Vhi). Output written as bf16 hi/lo for GEMM2.
// ===========================================================================
#define AT_PAD 136
#define AT_TILE_E (64 * AT_PAD)                 // elems per matrix tile
#define ATT_SMEM ((AT_TILE_E * (1 + 6)) * 2)    // Q + 2 stages x (K,Vh,Vl)

__global__ __launch_bounds__(128) void attn_hmma(
    const __nv_bfloat16* __restrict__ ah, const __nv_bfloat16* __restrict__ al,
    __nv_bfloat16* __restrict__ yhi, __nv_bfloat16* __restrict__ ylo)
{
    extern __shared__ __nv_bfloat16 smq[];
    const int tid  = threadIdx.x;
    const int wid  = tid >> 5;
    const int lane = tid & 31;
    const int qt = blockIdx.x;
    const int bh = blockIdx.y;
    const int b = bh >> 5, h = bh & 31, g = h >> 2, qi = h & 3;
    const size_t rowbase = (size_t)b * T_ * NQKV_ + g * 768;
    const __nv_bfloat16* qb = ah + rowbase + qi * 128;
    const __nv_bfloat16* kb = ah + rowbase + 512;
    const __nv_bfloat16* vh = ah + rowbase + 640;
    const __nv_bfloat16* vl = al + rowbase + 640;
    const int q0 = qt * 64;

    const uint32_t sb = smem_to_u32(smq);
    const uint32_t Qs = sb;
    uint32_t St[2];
    St[0] = sb + AT_TILE_E * 2;
    St[1] = St[0] + 3 * AT_TILE_E * 2;

    // Q tile loads (8 chunks/thread)
#pragma unroll
    for (int i = 0; i < 8; i++) {
        int idx = i * 128 + tid;
        int row = idx >> 4, ch = idx & 15;
        cp_async16(Qs + (uint32_t)(row * AT_PAD + ch * 8) * 2,
                   qb + (size_t)(q0 + row) * NQKV_ + ch * 8);
    }

    auto issue_kv = [&](int st, int k0) {
        uint32_t base = St[st];
#pragma unroll
        for (int i = 0; i < 24; i++) {
            int idx = i * 128 + tid;
            int arr = idx >> 10;
            int rem = idx & 1023;
            int row = rem >> 4, ch = rem & 15;
            const __nv_bfloat16* src =
                (arr == 0 ? kb : arr == 1 ? vh : vl) + (size_t)(k0 + row) * NQKV_ + ch * 8;
            cp_async16(base + (uint32_t)(arr * AT_TILE_E + row * AT_PAD + ch * 8) * 2, src);
        }
    };
    issue_kv(0, 0);
    cp_commit();

    float m_[2] = {-1e30f, -1e30f}, l_[2] = {0.f, 0.f};
    float O[16][4];
#pragma unroll
    for (int n = 0; n < 16; n++)
#pragma unroll
        for (int v = 0; v < 4; v++) O[n][v] = 0.f;

    const float sc = 0.08838834764831845f;
    const int r1 = lane >> 2;                  // row within m16 (+8 for regs 2,3)

    for (int kt = 0; kt <= qt; kt++) {
        const int st = kt & 1;
        if (kt < qt) {
            issue_kv(st ^ 1, (kt + 1) * 64);
            cp_commit();
            cp_wait<1>();
        } else {
            cp_wait<0>();
        }
        __syncthreads();

        const uint32_t Ks  = St[st];
        const uint32_t Vhs = St[st] + AT_TILE_E * 2;
        const uint32_t Vls = Vhs + AT_TILE_E * 2;

        // ---- S = Q K^T ----
        float s[8][4];
#pragma unroll
        for (int j = 0; j < 8; j++)
#pragma unroll
            for (int v = 0; v < 4; v++) s[j][v] = 0.f;

#pragma unroll
        for (int t = 0; t < 8; t++) {
            uint32_t a[4];
            ldsm4(a, Qs + (uint32_t)((wid * 16 + (lane & 15)) * AT_PAD +
                                     t * 16 + (lane >> 4) * 8) * 2);
#pragma unroll
            for (int u = 0; u < 4; u++) {
                uint32_t bb[4];
                ldsm4(bb, Ks + (uint32_t)((u * 16 + ((lane >> 4) << 3) + (lane & 7)) * AT_PAD +
                                          t * 16 + ((lane >> 3) & 1) * 8) * 2);
                mma_bf16(s[2 * u],     a, bb[0], bb[1]);
                mma_bf16(s[2 * u + 1], a, bb[2], bb[3]);
            }
        }

        // scale + causal mask
#pragma unroll
        for (int j = 0; j < 8; j++)
#pragma unroll
            for (int v = 0; v < 4; v++) s[j][v] *= sc;

        if (kt == qt) {
#pragma unroll
            for (int j = 0; j < 8; j++)
#pragma unroll
                for (int v = 0; v < 4; v++) {
                    int key = j * 8 + (lane & 3) * 2 + (v & 1);
                    int qr  = wid * 16 + r1 + ((v >> 1) << 3);
                    if (key > qr) s[j][v] = -1e30f;
                }
        }

        // ---- online softmax (2 rows per thread) ----
#pragma unroll
        for (int rr = 0; rr < 2; rr++) {
            float mx = -1e30f;
#pragma unroll
            for (int j = 0; j < 8; j++) {
                mx = fmaxf(mx, s[j][rr * 2]);
                mx = fmaxf(mx, s[j][rr * 2 + 1]);
            }
            mx = fmaxf(mx, __shfl_xor_sync(0xffffffffu, mx, 1));
            mx = fmaxf(mx, __shfl_xor_sync(0xffffffffu, mx, 2));
            float mnew = fmaxf(m_[rr], mx);
            float corr = __expf(m_[rr] - mnew);
            float sum = 0.f;
#pragma unroll
            for (int j = 0; j < 8; j++) {
                float p0 = __expf(s[j][rr * 2]     - mnew);
                float p1 = __expf(s[j][rr * 2 + 1] - mnew);
                s[j][rr * 2]     = p0;
                s[j][rr * 2 + 1] = p1;
                sum += p0 + p1;
            }
            sum += __shfl_xor_sync(0xffffffffu, sum, 1);
            sum += __shfl_xor_sync(0xffffffffu, sum, 2);
            l_[rr] = l_[rr] * corr + sum;
            m_[rr] = mnew;
#pragma unroll
            for (int n = 0; n < 16; n++) {
                O[n][rr * 2]     *= corr;
                O[n][rr * 2 + 1] *= corr;
            }
        }

        // ---- O += P V (split precision) ----
#pragma unroll
        for (int t = 0; t < 4; t++) {
            uint32_t phi[4], plo[4];
#pragma unroll
            for (int v = 0; v < 2; v++) {
                float p0 = s[2 * t][v * 2], p1 = s[2 * t][v * 2 + 1];
                float p2 = s[2 * t + 1][v * 2], p3 = s[2 * t + 1][v * 2 + 1];
                __nv_bfloat16 h0 = __float2bfloat16(p0), h1 = __float2bfloat16(p1);
                __nv_bfloat16 h2 = __float2bfloat16(p2), h3 = __float2bfloat16(p3);
                __nv_bfloat162 hp0 = __nv_bfloat162(h0, h1);
                __nv_bfloat162 hp1 = __nv_bfloat162(h2, h3);
                phi[v]     = *(uint32_t*)&hp0;
                phi[v + 2] = *(uint32_t*)&hp1;
                __nv_bfloat162 lp0 = __nv_bfloat162(
                    __float2bfloat16(p0 - __bfloat162float(h0)),
                    __float2bfloat16(p1 - __bfloat162float(h1)));
                __nv_bfloat162 lp1 = __nv_bfloat162(
                    __float2bfloat16(p2 - __bfloat162float(h2)),
                    __float2bfloat16(p3 - __bfloat162float(h3)));
                plo[v]     = *(uint32_t*)&lp0;
                plo[v + 2] = *(uint32_t*)&lp1;
            }
            // reorder: A regs = {a0=r/k, a1=r+8/k, a2=r/k+8, a3=r+8/k+8}
            uint32_t ahf[4] = {phi[0], phi[1], phi[2], phi[3]};
            uint32_t alf[4] = {plo[0], plo[1], plo[2], plo[3]};
#pragma unroll
            for (int dg = 0; dg < 8; dg++) {
                uint32_t roff = (uint32_t)((t * 16 + ((lane >> 3) & 1) * 8 + (lane & 7)) * AT_PAD +
                                           dg * 16 + (lane >> 4) * 8) * 2;
                uint32_t bhv[4], blv[4];
                ldsm4t(bhv, Vhs + roff);
                ldsm4t(blv, Vls + roff);
                mma_bf16(O[2 * dg],     ahf, bhv[0], bhv[1]);
                mma_bf16(O[2 * dg + 1], ahf, bhv[2], bhv[3]);
                mma_bf16(O[2 * dg],     ahf, blv[0], blv[1]);
                mma_bf16(O[2 * dg + 1], ahf, blv[2], blv[3]);
                mma_bf16(O[2 * dg],     alf, bhv[0], bhv[1]);
                mma_bf16(O[2 * dg + 1], alf, bhv[2], bhv[3]);
            }
        }
        __syncthreads();
    }

    // Epilogue: normalize, write y as bf16 hi/lo
#pragma unroll
    for (int rr = 0; rr < 2; rr++) {
        float inv = 1.f / l_[rr];
        int row = q0 + wid * 16 + r1 + rr * 8;
        size_t rb = (size_t)(b * T_ + row) * C_ + h * 128;
#pragma unroll
        for (int n = 0; n < 16; n++) {
            int col = n * 8 + (lane & 3) * 2;
            float o0 = O[n][rr * 2] * inv;
            float o1 = O[n][rr * 2 + 1] * inv;
            __nv_bfloat16 h0 = __float2bfloat16(o0);
            __nv_bfloat16 h1 = __float2bfloat16(o1);
            __nv_bfloat162 hp = __nv_bfloat162(h0, h1);
            __nv_bfloat162 lp = __nv_bfloat162(
                __float2bfloat16(o0 - __bfloat162float(h0)),
                __float2bfloat16(o1 - __bfloat162float(h1)));
            *(uint32_t*)(yhi + rb + col) = *(uint32_t*)&hp;
            *(uint32_t*)(ylo + rb + col) = *(uint32_t*)&lp;
        }
    }
}

// ===========================================================================
// Launch
// ===========================================================================
extern "C" void kernel_launch(void* const* d_in, const int* in_sizes, int n_in,
                              void* d_out, int out_size)
{
    const float* x     = (const float*)d_in[0];
    const float* cosb  = (const float*)d_in[1];
    const float* sinb  = (const float*)d_in[2];
    const float* Wqkv  = (const float*)d_in[3];
    const float* Wproj = (const float*)d_in[4];
    float* out = (float*)d_out;

    float* qkv = nullptr;
    __nv_bfloat16 *atth, *attl, *ahi, *alo, *bhi, *blo;
    cudaGetSymbolAddress((void**)&qkv,  g_qkv);
    cudaGetSymbolAddress((void**)&atth, g_att_hi);
    cudaGetSymbolAddress((void**)&attl, g_att_lo);
    cudaGetSymbolAddress((void**)&ahi,  g_a_hi);
    cudaGetSymbolAddress((void**)&alo,  g_a_lo);
    cudaGetSymbolAddress((void**)&bhi,  g_b_hi);
    cudaGetSymbolAddress((void**)&blo,  g_b_lo);

    cudaFuncSetAttribute(hmma_gemm, cudaFuncAttributeMaxDynamicSharedMemorySize,
                         GEMM_SMEM);
    cudaFuncSetAttribute(attn_hmma, cudaFuncAttributeMaxDynamicSharedMemorySize,
                         ATT_SMEM);

    // ---- GEMM 1: qkv = x @ Wqkv^T ----
    {
        int n4a = M_ * C_ / 4, n4b = NQKV_ * C_ / 4;
        split_bf16_kernel<<<(n4a + 255) / 256, 256>>>(x, ahi, alo, n4a);
        split_bf16_kernel<<<(n4b + 255) / 256, 256>>>(Wqkv, bhi, blo, n4b);
        hmma_gemm<<<dim3(M_ / BM, NQKV_ / BN), 256, GEMM_SMEM>>>(
            ahi, alo, bhi, blo, qkv, NQKV_, C_);
    }

    // ---- RoPE + bf16 conversion ----
    {
        int total = M_ * NG_ * 6 * 64;
        rope_split_kernel<<<(total + 255) / 256, 256>>>(qkv, cosb, sinb, atth, attl);
    }

    // ---- HMMA attention -> y (bf16 hi/lo directly into GEMM2 A buffers) ----
    attn_hmma<<<dim3(T_ / 64, B_ * NH_), 128, ATT_SMEM>>>(atth, attl, ahi, alo);

    // ---- GEMM 2: out = y @ Wproj^T ----
    {
        int n4b = C_ * C_ / 4;
        split_bf16_kernel<<<(n4b + 255) / 256, 256>>>(Wproj, bhi, blo, n4b);
        hmma_gemm<<<dim3(M_ / BM, C_ / BN), 256, GEMM_SMEM>>>(
            ahi, alo, bhi, blo, out, C_, C_);
    }
}

// round 6
// speedup vs baseline: 2.9121x; 1.0526x over previous
#include <cuda_runtime.h>
#include <cuda_bf16.h>
#include <math.h>
#include <stdint.h>

// Problem constants
#define B_    2
#define T_    2048
#define C_    4096
#define NH_   32
#define NG_   8
#define HS_   128
#define M_    (B_ * T_)                 // 4096 rows
#define NQKV_ ((NH_ + 2 * NG_) * HS_)   // 6144

// Scratch (no cudaMalloc allowed)
__device__ float g_qkv[(size_t)M_ * NQKV_];               // 100.7 MB fp32 qkv
__device__ __nv_bfloat16 g_att_hi[(size_t)M_ * NQKV_];    // 50 MB
__device__ __nv_bfloat16 g_att_lo[(size_t)M_ * NQKV_];    // 50 MB
__device__ __nv_bfloat16 g_a_hi[(size_t)M_ * C_];         // 32 MB
__device__ __nv_bfloat16 g_a_lo[(size_t)M_ * C_];         // 32 MB
__device__ __nv_bfloat16 g_b_hi[(size_t)NQKV_ * C_];      // 48 MB
__device__ __nv_bfloat16 g_b_lo[(size_t)NQKV_ * C_];      // 48 MB

// ===========================================================================
// PTX helpers
// ===========================================================================
__device__ __forceinline__ uint32_t smem_to_u32(const void* p) {
    uint32_t a;
    asm("{ .reg .u64 t; cvta.to.shared.u64 t, %1; cvt.u32.u64 %0, t; }"
        : "=r"(a) : "l"(p));
    return a;
}
__device__ __forceinline__ void cp_async16(uint32_t dst, const void* src) {
    asm volatile("cp.async.cg.shared.global [%0], [%1], 16;" :: "r"(dst), "l"(src));
}
__device__ __forceinline__ void cp_commit() {
    asm volatile("cp.async.commit_group;");
}
template <int N> __device__ __forceinline__ void cp_wait() {
    asm volatile("cp.async.wait_group %0;" :: "n"(N));
}
__device__ __forceinline__ void ldsm4(uint32_t* r, uint32_t addr) {
    asm volatile("ldmatrix.sync.aligned.m8n8.x4.shared.b16 {%0,%1,%2,%3}, [%4];"
        : "=r"(r[0]), "=r"(r[1]), "=r"(r[2]), "=r"(r[3]) : "r"(addr));
}
__device__ __forceinline__ void ldsm4t(uint32_t* r, uint32_t addr) {
    asm volatile("ldmatrix.sync.aligned.m8n8.x4.trans.shared.b16 {%0,%1,%2,%3}, [%4];"
        : "=r"(r[0]), "=r"(r[1]), "=r"(r[2]), "=r"(r[3]) : "r"(addr));
}
__device__ __forceinline__ void mma_bf16(float* d, const uint32_t* a,
                                         uint32_t b0, uint32_t b1) {
    asm volatile(
        "mma.sync.aligned.m16n8k16.row.col.f32.bf16.bf16.f32 "
        "{%0,%1,%2,%3}, {%4,%5,%6,%7}, {%8,%9}, {%0,%1,%2,%3};"
        : "+f"(d[0]), "+f"(d[1]), "+f"(d[2]), "+f"(d[3])
        : "r"(a[0]), "r"(a[1]), "r"(a[2]), "r"(a[3]), "r"(b0), "r"(b1));
}

// ===========================================================================
// HMMA GEMM: C = Ahi@Bhi^T + Ahi@Blo^T + Alo@Bhi^T.
// 128x128x32 tiles, 256 threads (8 warps 4x2), 4-stage cp.async pipeline
// (3 loads in flight, chunk c -> slot c%4), pass-reordered MMAs.
// ===========================================================================
#define BM 128
#define BN 128
#define BK 32
#define PADK 40
#define MAT_ELEMS (128 * PADK)            // 5120 bf16
#define STAGE_ELEMS (4 * MAT_ELEMS)       // 20480 bf16
#define NSTAGE 4
#define GEMM_SMEM (NSTAGE * STAGE_ELEMS * 2)   // 163840 B

__global__ __launch_bounds__(256) void hmma_gemm(
    const __nv_bfloat16* __restrict__ Ahi, const __nv_bfloat16* __restrict__ Alo,
    const __nv_bfloat16* __restrict__ Bhi, const __nv_bfloat16* __restrict__ Blo,
    float* __restrict__ C, int Ntot, int K)
{
    extern __shared__ __nv_bfloat16 smb[];
    const int tid  = threadIdx.x;
    const int wid  = tid >> 5;
    const int lane = tid & 31;
    const int wm   = wid & 3;
    const int wn   = wid >> 2;
    const int m0   = blockIdx.x * BM;
    const int n0   = blockIdx.y * BN;
    const uint32_t sbase = smem_to_u32(smb);

    float acc[2][8][4];
#pragma unroll
    for (int i = 0; i < 2; i++)
#pragma unroll
        for (int j = 0; j < 8; j++)
#pragma unroll
            for (int v = 0; v < 4; v++) acc[i][j][v] = 0.f;

    auto issue_stage = [&](int s, int k0) {
        uint32_t dstb = sbase + s * (STAGE_ELEMS * 2);
#pragma unroll
        for (int i = 0; i < 8; i++) {
            int idx = i * 256 + tid;
            int mat = idx >> 9;
            int rem = idx & 511;
            int row = rem >> 2;
            int ch  = rem & 3;
            int grow = (mat < 2) ? (m0 + row) : (n0 + row);
            const __nv_bfloat16* base =
                (mat == 0) ? Ahi : (mat == 1) ? Alo : (mat == 2) ? Bhi : Blo;
            const __nv_bfloat16* src = base + (size_t)grow * K + k0 + ch * 8;
            uint32_t d = dstb + (uint32_t)(mat * MAT_ELEMS + row * PADK + ch * 8) * 2;
            cp_async16(d, src);
        }
    };

    // Hoisted per-thread ldsm offsets (within a stage)
    const uint32_t offA = (uint32_t)((wm * 32 + (lane & 15)) * PADK + (lane >> 4) * 8) * 2;
    const uint32_t offB = (uint32_t)(2 * MAT_ELEMS +
        (wn * 64 + (lane & 7) + ((lane >> 4) << 3)) * PADK + ((lane >> 3) & 1) * 8) * 2;

    issue_stage(0, 0);        cp_commit();
    issue_stage(1, BK);       cp_commit();
    issue_stage(2, 2 * BK);   cp_commit();

    const int nk = K / BK;
    for (int it = 0; it < nk; it++) {
        if (it + 2 < nk)      cp_wait<2>();
        else if (it + 1 < nk) cp_wait<1>();
        else                  cp_wait<0>();
        __syncthreads();

        // chunk `it` lives in slot it % NSTAGE
        const uint32_t stb = sbase + (it & (NSTAGE - 1)) * (STAGE_ELEMS * 2);
#pragma unroll
        for (int kk = 0; kk < 2; kk++) {
            uint32_t ah[2][4], al[2][4], bh[4][4], bl[4][4];
#pragma unroll
            for (int mt = 0; mt < 2; mt++) {
                uint32_t a = stb + offA + (uint32_t)(mt * 16 * PADK + kk * 16) * 2;
                ldsm4(ah[mt], a);
                ldsm4(al[mt], a + MAT_ELEMS * 2);
            }
#pragma unroll
            for (int nt = 0; nt < 4; nt++) {
                uint32_t a = stb + offB + (uint32_t)(nt * 16 * PADK + kk * 16) * 2;
                ldsm4(bh[nt], a);
                ldsm4(bl[nt], a + MAT_ELEMS * 2);
            }
            // pass 1: Ahi * Bhi over all 16 accumulators
#pragma unroll
            for (int mt = 0; mt < 2; mt++)
#pragma unroll
                for (int n8 = 0; n8 < 8; n8++)
                    mma_bf16(acc[mt][n8], ah[mt],
                             bh[n8 >> 1][(n8 & 1) * 2], bh[n8 >> 1][(n8 & 1) * 2 + 1]);
            // pass 2: Ahi * Blo
#pragma unroll
            for (int mt = 0; mt < 2; mt++)
#pragma unroll
                for (int n8 = 0; n8 < 8; n8++)
                    mma_bf16(acc[mt][n8], ah[mt],
                             bl[n8 >> 1][(n8 & 1) * 2], bl[n8 >> 1][(n8 & 1) * 2 + 1]);
            // pass 3: Alo * Bhi
#pragma unroll
            for (int mt = 0; mt < 2; mt++)
#pragma unroll
                for (int n8 = 0; n8 < 8; n8++)
                    mma_bf16(acc[mt][n8], al[mt],
                             bh[n8 >> 1][(n8 & 1) * 2], bh[n8 >> 1][(n8 & 1) * 2 + 1]);
        }
        __syncthreads();
        if (it + 3 < nk) {
            issue_stage((it + 3) & (NSTAGE - 1), (it + 3) * BK);
            cp_commit();
        }
    }

#pragma unroll
    for (int mt = 0; mt < 2; mt++) {
        int r0 = m0 + wm * 32 + mt * 16 + (lane >> 2);
#pragma unroll
        for (int n8 = 0; n8 < 8; n8++) {
            int col = n0 + wn * 64 + n8 * 8 + (lane & 3) * 2;
            *(float2*)(C + (size_t)r0 * Ntot + col) =
                make_float2(acc[mt][n8][0], acc[mt][n8][1]);
            *(float2*)(C + (size_t)(r0 + 8) * Ntot + col) =
                make_float2(acc[mt][n8][2], acc[mt][n8][3]);
        }
    }
}

// ===========================================================================
// fp32 -> bf16 hi/lo split; 8 elements per thread
// ===========================================================================
__global__ void split_bf16_kernel(const float* __restrict__ in,
                                  __nv_bfloat16* __restrict__ hi,
                                  __nv_bfloat16* __restrict__ lo, int n8)
{
    int i = blockIdx.x * blockDim.x + threadIdx.x;
    if (i >= n8) return;
    float4 va = *(const float4*)(in + (size_t)i * 8);
    float4 vb = *(const float4*)(in + (size_t)i * 8 + 4);
    float f[8] = {va.x, va.y, va.z, va.w, vb.x, vb.y, vb.z, vb.w};
    uint32_t hw[4], lw[4];
#pragma unroll
    for (int j = 0; j < 4; j++) {
        __nv_bfloat16 h0 = __float2bfloat16(f[2 * j]);
        __nv_bfloat16 h1 = __float2bfloat16(f[2 * j + 1]);
        __nv_bfloat162 hp = __nv_bfloat162(h0, h1);
        __nv_bfloat162 lp = __nv_bfloat162(
            __float2bfloat16(f[2 * j]     - __bfloat162float(h0)),
            __float2bfloat16(f[2 * j + 1] - __bfloat162float(h1)));
        hw[j] = *(uint32_t*)&hp;
        lw[j] = *(uint32_t*)&lp;
    }
    *(uint4*)(hi + (size_t)i * 8) = make_uint4(hw[0], hw[1], hw[2], hw[3]);
    *(uint4*)(lo + (size_t)i * 8) = make_uint4(lw[0], lw[1], lw[2], lw[3]);
}

// ===========================================================================
// RoPE + bf16 conversion, vectorized x4: q,k roped -> att_hi;
// v hi/lo split -> att_hi/att_lo.
// ===========================================================================
__global__ void rope_split_kernel(const float* __restrict__ qkv,
                                  const float* __restrict__ cs,
                                  const float* __restrict__ sn,
                                  __nv_bfloat16* __restrict__ ah,
                                  __nv_bfloat16* __restrict__ al)
{
    int idx = blockIdx.x * blockDim.x + threadIdx.x;
    const int total = M_ * NG_ * 6 * 16;
    if (idx >= total) return;

    int d4 = (idx & 15) * 4;
    int r = idx >> 4;
    int slot = r % 6; r /= 6;
    int g    = r % NG_; r /= NG_;
    int t = r & (T_ - 1);

    size_t off = (size_t)r * NQKV_ + g * 768 + slot * 128;
    const float* p = qkv + off;
    float4 x1 = *(const float4*)(p + d4);
    float4 x2 = *(const float4*)(p + d4 + 64);
    float o1[4], o2[4];

    if (slot < 5) {
        float4 c1 = *(const float4*)(cs + t * HS_ + d4);
        float4 s1 = *(const float4*)(sn + t * HS_ + d4);
        float4 c2 = *(const float4*)(cs + t * HS_ + d4 + 64);
        float4 s2 = *(const float4*)(sn + t * HS_ + d4 + 64);
        o1[0] = x1.x * c1.x - x2.x * s1.x;  o2[0] = x2.x * c2.x + x1.x * s2.x;
        o1[1] = x1.y * c1.y - x2.y * s1.y;  o2[1] = x2.y * c2.y + x1.y * s2.y;
        o1[2] = x1.z * c1.z - x2.z * s1.z;  o2[2] = x2.z * c2.z + x1.z * s2.z;
        o1[3] = x1.w * c1.w - x2.w * s1.w;  o2[3] = x2.w * c2.w + x1.w * s2.w;
        uint32_t w1[2], w2[2];
#pragma unroll
        for (int j = 0; j < 2; j++) {
            __nv_bfloat162 p1 = __nv_bfloat162(__float2bfloat16(o1[2 * j]),
                                               __float2bfloat16(o1[2 * j + 1]));
            __nv_bfloat162 p2 = __nv_bfloat162(__float2bfloat16(o2[2 * j]),
                                               __float2bfloat16(o2[2 * j + 1]));
            w1[j] = *(uint32_t*)&p1;
            w2[j] = *(uint32_t*)&p2;
        }
        *(uint2*)(ah + off + d4)      = make_uint2(w1[0], w1[1]);
        *(uint2*)(ah + off + d4 + 64) = make_uint2(w2[0], w2[1]);
    } else {
        float v[8] = {x1.x, x1.y, x1.z, x1.w, x2.x, x2.y, x2.z, x2.w};
        uint32_t hw[4], lw[4];
#pragma unroll
        for (int j = 0; j < 4; j++) {
            __nv_bfloat16 h0 = __float2bfloat16(v[2 * j]);
            __nv_bfloat16 h1 = __float2bfloat16(v[2 * j + 1]);
            __nv_bfloat162 hp = __nv_bfloat162(h0, h1);
            __nv_bfloat162 lp = __nv_bfloat162(
                __float2bfloat16(v[2 * j]     - __bfloat162float(h0)),
                __float2bfloat16(v[2 * j + 1] - __bfloat162float(h1)));
            hw[j] = *(uint32_t*)&hp;
            lw[j] = *(uint32_t*)&lp;
        }
        *(uint2*)(ah + off + d4)      = make_uint2(hw[0], hw[1]);
        *(uint2*)(ah + off + d4 + 64) = make_uint2(hw[2], hw[3]);
        *(uint2*)(al + off + d4)      = make_uint2(lw[0], lw[1]);
        *(uint2*)(al + off + d4 + 64) = make_uint2(lw[2], lw[3]);
    }
}

// ===========================================================================
// HMMA causal flash attention. 256 thr (8 warps), 128 q-rows/block,
// 64-key tiles double-buffered. QK bf16; PV split precision.
// Output bf16 hi/lo.
// ===========================================================================
#define AT_PAD 136
#define AT_TILE_E (64 * AT_PAD)
#define AT_Q_E (128 * AT_PAD)
#define ATT_SMEM ((AT_Q_E + 6 * AT_TILE_E) * 2)   // 139264 B

__global__ __launch_bounds__(256) void attn_hmma(
    const __nv_bfloat16* __restrict__ ah, const __nv_bfloat16* __restrict__ al,
    __nv_bfloat16* __restrict__ yhi, __nv_bfloat16* __restrict__ ylo)
{
    extern __shared__ __nv_bfloat16 smq[];
    const int tid  = threadIdx.x;
    const int wid  = tid >> 5;
    const int lane = tid & 31;
    const int qtb = gridDim.x - 1 - blockIdx.x;   // big blocks first
    const int bh = blockIdx.y;
    const int b = bh >> 5, h = bh & 31, g = h >> 2, qi = h & 3;
    const size_t rowbase = (size_t)b * T_ * NQKV_ + g * 768;
    const __nv_bfloat16* qb = ah + rowbase + qi * 128;
    const __nv_bfloat16* kb = ah + rowbase + 512;
    const __nv_bfloat16* vh = ah + rowbase + 640;
    const __nv_bfloat16* vl = al + rowbase + 640;
    const int q0 = qtb * 128;
    const int ntiles = 2 * qtb + 2;

    const uint32_t sb = smem_to_u32(smq);
    const uint32_t Qs = sb;
    uint32_t St[2];
    St[0] = sb + AT_Q_E * 2;
    St[1] = St[0] + 3 * AT_TILE_E * 2;

    // Q tile: 128 rows x 16 chunks
#pragma unroll
    for (int i = 0; i < 8; i++) {
        int idx = i * 256 + tid;
        int row = idx >> 4, ch = idx & 15;
        cp_async16(Qs + (uint32_t)(row * AT_PAD + ch * 8) * 2,
                   qb + (size_t)(q0 + row) * NQKV_ + ch * 8);
    }

    auto issue_kv = [&](int st, int k0) {
        uint32_t base = St[st];
#pragma unroll
        for (int i = 0; i < 12; i++) {
            int idx = i * 256 + tid;
            int arr = idx >> 10;
            int rem = idx & 1023;
            int row = rem >> 4, ch = rem & 15;
            const __nv_bfloat16* src =
                (arr == 0 ? kb : arr == 1 ? vh : vl) + (size_t)(k0 + row) * NQKV_ + ch * 8;
            cp_async16(base + (uint32_t)(arr * AT_TILE_E + row * AT_PAD + ch * 8) * 2, src);
        }
    };
    issue_kv(0, 0);
    cp_commit();

    float m_[2] = {-1e30f, -1e30f}, l_[2] = {0.f, 0.f};
    float O[16][4];
#pragma unroll
    for (int n = 0; n < 16; n++)
#pragma unroll
        for (int v = 0; v < 4; v++) O[n][v] = 0.f;

    const float sc = 0.08838834764831845f;
    const int r1 = lane >> 2;
    const int qw = q0 + wid * 16;            // warp's first q row (global)

    for (int kt = 0; kt < ntiles; kt++) {
        const int st = kt & 1;
        const int k0 = kt * 64;
        if (kt + 1 < ntiles) {
            issue_kv(st ^ 1, (kt + 1) * 64);
            cp_commit();
            cp_wait<1>();
        } else {
            cp_wait<0>();
        }
        __syncthreads();

        const uint32_t Ks  = St[st];
        const uint32_t Vhs = St[st] + AT_TILE_E * 2;
        const uint32_t Vls = Vhs + AT_TILE_E * 2;

        // ---- S = Q K^T ----
        float s[8][4];
#pragma unroll
        for (int j = 0; j < 8; j++)
#pragma unroll
            for (int v = 0; v < 4; v++) s[j][v] = 0.f;

#pragma unroll
        for (int t = 0; t < 8; t++) {
            uint32_t a[4];
            ldsm4(a, Qs + (uint32_t)((wid * 16 + (lane & 15)) * AT_PAD +
                                     t * 16 + (lane >> 4) * 8) * 2);
#pragma unroll
            for (int u = 0; u < 4; u++) {
                uint32_t bb[4];
                ldsm4(bb, Ks + (uint32_t)((u * 16 + ((lane >> 4) << 3) + (lane & 7)) * AT_PAD +
                                          t * 16 + ((lane >> 3) & 1) * 8) * 2);
                mma_bf16(s[2 * u],     a, bb[0], bb[1]);
                mma_bf16(s[2 * u + 1], a, bb[2], bb[3]);
            }
        }

#pragma unroll
        for (int j = 0; j < 8; j++)
#pragma unroll
            for (int v = 0; v < 4; v++) s[j][v] *= sc;

        if (k0 + 63 > qw) {   // tile touches/exceeds this warp's causal boundary
#pragma unroll
            for (int j = 0; j < 8; j++)
#pragma unroll
                for (int v = 0; v < 4; v++) {
                    int key = k0 + j * 8 + (lane & 3) * 2 + (v & 1);
                    int qr  = qw + r1 + ((v >> 1) << 3);
                    if (key > qr) s[j][v] = -1e30f;
                }
        }

        // ---- online softmax ----
#pragma unroll
        for (int rr = 0; rr < 2; rr++) {
            float mx = -1e30f;
#pragma unroll
            for (int j = 0; j < 8; j++) {
                mx = fmaxf(mx, s[j][rr * 2]);
                mx = fmaxf(mx, s[j][rr * 2 + 1]);
            }
            mx = fmaxf(mx, __shfl_xor_sync(0xffffffffu, mx, 1));
            mx = fmaxf(mx, __shfl_xor_sync(0xffffffffu, mx, 2));
            float mnew = fmaxf(m_[rr], mx);
            float corr = __expf(m_[rr] - mnew);
            float sum = 0.f;
#pragma unroll
            for (int j = 0; j < 8; j++) {
                float p0 = __expf(s[j][rr * 2]     - mnew);
                float p1 = __expf(s[j][rr * 2 + 1] - mnew);
                s[j][rr * 2]     = p0;
                s[j][rr * 2 + 1] = p1;
                sum += p0 + p1;
            }
            sum += __shfl_xor_sync(0xffffffffu, sum, 1);
            sum += __shfl_xor_sync(0xffffffffu, sum, 2);
            l_[rr] = l_[rr] * corr + sum;
            m_[rr] = mnew;
#pragma unroll
            for (int n = 0; n < 16; n++) {
                O[n][rr * 2]     *= corr;
                O[n][rr * 2 + 1] *= corr;
            }
        }

        // ---- O += P V (split precision) ----
#pragma unroll
        for (int t = 0; t < 4; t++) {
            uint32_t phi[4], plo[4];
#pragma unroll
            for (int v = 0; v < 2; v++) {
                float p0 = s[2 * t][v * 2], p1 = s[2 * t][v * 2 + 1];
                float p2 = s[2 * t + 1][v * 2], p3 = s[2 * t + 1][v * 2 + 1];
                __nv_bfloat16 h0 = __float2bfloat16(p0), h1 = __float2bfloat16(p1);
                __nv_bfloat16 h2 = __float2bfloat16(p2), h3 = __float2bfloat16(p3);
                __nv_bfloat162 hp0 = __nv_bfloat162(h0, h1);
                __nv_bfloat162 hp1 = __nv_bfloat162(h2, h3);
                phi[v]     = *(uint32_t*)&hp0;
                phi[v + 2] = *(uint32_t*)&hp1;
                __nv_bfloat162 lp0 = __nv_bfloat162(
                    __float2bfloat16(p0 - __bfloat162float(h0)),
                    __float2bfloat16(p1 - __bfloat162float(h1)));
                __nv_bfloat162 lp1 = __nv_bfloat162(
                    __float2bfloat16(p2 - __bfloat162float(h2)),
                    __float2bfloat16(p3 - __bfloat162float(h3)));
                plo[v]     = *(uint32_t*)&lp0;
                plo[v + 2] = *(uint32_t*)&lp1;
            }
#pragma unroll
            for (int dg = 0; dg < 8; dg++) {
                uint32_t roff = (uint32_t)((t * 16 + ((lane >> 3) & 1) * 8 + (lane & 7)) * AT_PAD +
                                           dg * 16 + (lane >> 4) * 8) * 2;
                uint32_t bhv[4], blv[4];
                ldsm4t(bhv, Vhs + roff);
                ldsm4t(blv, Vls + roff);
                mma_bf16(O[2 * dg],     phi, bhv[0], bhv[1]);
                mma_bf16(O[2 * dg + 1], phi, bhv[2], bhv[3]);
                mma_bf16(O[2 * dg],     phi, blv[0], blv[1]);
                mma_bf16(O[2 * dg + 1], phi, blv[2], blv[3]);
                mma_bf16(O[2 * dg],     plo, bhv[0], bhv[1]);
                mma_bf16(O[2 * dg + 1], plo, bhv[2], bhv[3]);
            }
        }
        __syncthreads();
    }

    // Epilogue: normalize, write bf16 hi/lo
#pragma unroll
    for (int rr = 0; rr < 2; rr++) {
        float inv = 1.f / l_[rr];
        int row = qw + r1 + rr * 8;
        size_t rb = (size_t)(b * T_ + row) * C_ + h * 128;
#pragma unroll
        for (int n = 0; n < 16; n++) {
            int col = n * 8 + (lane & 3) * 2;
            float o0 = O[n][rr * 2] * inv;
            float o1 = O[n][rr * 2 + 1] * inv;
            __nv_bfloat16 h0 = __float2bfloat16(o0);
            __nv_bfloat16 h1 = __float2bfloat16(o1);
            __nv_bfloat162 hp = __nv_bfloat162(h0, h1);
            __nv_bfloat162 lp = __nv_bfloat162(
                __float2bfloat16(o0 - __bfloat162float(h0)),
                __float2bfloat16(o1 - __bfloat162float(h1)));
            *(uint32_t*)(yhi + rb + col) = *(uint32_t*)&hp;
            *(uint32_t*)(ylo + rb + col) = *(uint32_t*)&lp;
        }
    }
}

// ===========================================================================
// Launch
// ===========================================================================
extern "C" void kernel_launch(void* const* d_in, const int* in_sizes, int n_in,
                              void* d_out, int out_size)
{
    const float* x     = (const float*)d_in[0];
    const float* cosb  = (const float*)d_in[1];
    const float* sinb  = (const float*)d_in[2];
    const float* Wqkv  = (const float*)d_in[3];
    const float* Wproj = (const float*)d_in[4];
    float* out = (float*)d_out;

    float* qkv = nullptr;
    __nv_bfloat16 *atth, *attl, *ahi, *alo, *bhi, *blo;
    cudaGetSymbolAddress((void**)&qkv,  g_qkv);
    cudaGetSymbolAddress((void**)&atth, g_att_hi);
    cudaGetSymbolAddress((void**)&attl, g_att_lo);
    cudaGetSymbolAddress((void**)&ahi,  g_a_hi);
    cudaGetSymbolAddress((void**)&alo,  g_a_lo);
    cudaGetSymbolAddress((void**)&bhi,  g_b_hi);
    cudaGetSymbolAddress((void**)&blo,  g_b_lo);

    cudaFuncSetAttribute(hmma_gemm, cudaFuncAttributeMaxDynamicSharedMemorySize,
                         GEMM_SMEM);
    cudaFuncSetAttribute(attn_hmma, cudaFuncAttributeMaxDynamicSharedMemorySize,
                         ATT_SMEM);

    // ---- GEMM 1: qkv = x @ Wqkv^T ----
    {
        int n8a = M_ * C_ / 8, n8b = NQKV_ * C_ / 8;
        split_bf16_kernel<<<(n8a + 255) / 256, 256>>>(x, ahi, alo, n8a);
        split_bf16_kernel<<<(n8b + 255) / 256, 256>>>(Wqkv, bhi, blo, n8b);
        hmma_gemm<<<dim3(M_ / BM, NQKV_ / BN), 256, GEMM_SMEM>>>(
            ahi, alo, bhi, blo, qkv, NQKV_, C_);
    }

    // ---- RoPE + bf16 conversion ----
    {
        int total = M_ * NG_ * 6 * 16;
        rope_split_kernel<<<(total + 255) / 256, 256>>>(qkv, cosb, sinb, atth, attl);
    }

    // ---- HMMA attention -> y (bf16 hi/lo into GEMM2 A buffers) ----
    attn_hmma<<<dim3(T_ / 128, B_ * NH_), 256, ATT_SMEM>>>(atth, attl, ahi, alo);

    // ---- GEMM 2: out = y @ Wproj^T ----
    {
        int n8b = C_ * C_ / 8;
        split_bf16_kernel<<<(n8b + 255) / 256, 256>>>(Wproj, bhi, blo, n8b);
        hmma_gemm<<<dim3(M_ / BM, C_ / BN), 256, GEMM_SMEM>>>(
            ahi, alo, bhi, blo, out, C_, C_);
    }
}

// round 7
// speedup vs baseline: 3.2789x; 1.1260x over previous
#include <cuda_runtime.h>
#include <cuda_bf16.h>
#include <math.h>
#include <stdint.h>

// Problem constants
#define B_    2
#define T_    2048
#define C_    4096
#define NH_   32
#define NG_   8
#define HS_   128
#define M_    (B_ * T_)                 // 4096 rows
#define NQKV_ ((NH_ + 2 * NG_) * HS_)   // 6144

// Scratch (no cudaMalloc allowed)
__device__ float g_qkv[(size_t)M_ * NQKV_];               // 100.7 MB fp32 qkv
__device__ __nv_bfloat16 g_att_hi[(size_t)M_ * NQKV_];    // 50 MB
__device__ __nv_bfloat16 g_att_lo[(size_t)M_ * NQKV_];    // 50 MB
__device__ __nv_bfloat16 g_a_hi[(size_t)M_ * C_];         // 32 MB
__device__ __nv_bfloat16 g_a_lo[(size_t)M_ * C_];         // 32 MB
__device__ __nv_bfloat16 g_b_hi[(size_t)NQKV_ * C_];      // 48 MB
__device__ __nv_bfloat16 g_b_lo[(size_t)NQKV_ * C_];      // 48 MB

// ===========================================================================
// PTX helpers
// ===========================================================================
__device__ __forceinline__ uint32_t smem_to_u32(const void* p) {
    uint32_t a;
    asm("{ .reg .u64 t; cvta.to.shared.u64 t, %1; cvt.u32.u64 %0, t; }"
        : "=r"(a) : "l"(p));
    return a;
}
__device__ __forceinline__ void cp_async16(uint32_t dst, const void* src) {
    asm volatile("cp.async.cg.shared.global [%0], [%1], 16;" :: "r"(dst), "l"(src));
}
__device__ __forceinline__ void cp_commit() {
    asm volatile("cp.async.commit_group;");
}
template <int N> __device__ __forceinline__ void cp_wait() {
    asm volatile("cp.async.wait_group %0;" :: "n"(N));
}
__device__ __forceinline__ void ldsm4(uint32_t* r, uint32_t addr) {
    asm volatile("ldmatrix.sync.aligned.m8n8.x4.shared.b16 {%0,%1,%2,%3}, [%4];"
        : "=r"(r[0]), "=r"(r[1]), "=r"(r[2]), "=r"(r[3]) : "r"(addr));
}
__device__ __forceinline__ void ldsm4t(uint32_t* r, uint32_t addr) {
    asm volatile("ldmatrix.sync.aligned.m8n8.x4.trans.shared.b16 {%0,%1,%2,%3}, [%4];"
        : "=r"(r[0]), "=r"(r[1]), "=r"(r[2]), "=r"(r[3]) : "r"(addr));
}
__device__ __forceinline__ void mma_bf16(float* d, const uint32_t* a,
                                         uint32_t b0, uint32_t b1) {
    asm volatile(
        "mma.sync.aligned.m16n8k16.row.col.f32.bf16.bf16.f32 "
        "{%0,%1,%2,%3}, {%4,%5,%6,%7}, {%8,%9}, {%0,%1,%2,%3};"
        : "+f"(d[0]), "+f"(d[1]), "+f"(d[2]), "+f"(d[3])
        : "r"(a[0]), "r"(a[1]), "r"(a[2]), "r"(a[3]), "r"(b0), "r"(b1));
}

// ===========================================================================
// HMMA GEMM: C = Ahi@Bhi^T + Ahi@Blo^T + Alo@Bhi^T.
// 128x128x32 tiles, 256 threads (8 warps 4x2), 2-stage double buffer,
// 80KB smem -> 2 CTAs/SM for bubble-filling occupancy.
// ===========================================================================
#define BM 128
#define BN 128
#define BK 32
#define PADK 40
#define MAT_ELEMS (128 * PADK)            // 5120 bf16
#define STAGE_ELEMS (4 * MAT_ELEMS)       // 20480 bf16
#define NSTAGE 2
#define GEMM_SMEM (NSTAGE * STAGE_ELEMS * 2)   // 81920 B

__global__ __launch_bounds__(256, 2) void hmma_gemm(
    const __nv_bfloat16* __restrict__ Ahi, const __nv_bfloat16* __restrict__ Alo,
    const __nv_bfloat16* __restrict__ Bhi, const __nv_bfloat16* __restrict__ Blo,
    float* __restrict__ C, int Ntot, int K)
{
    extern __shared__ __nv_bfloat16 smb[];
    const int tid  = threadIdx.x;
    const int wid  = tid >> 5;
    const int lane = tid & 31;
    const int wm   = wid & 3;
    const int wn   = wid >> 2;
    const int m0   = blockIdx.x * BM;
    const int n0   = blockIdx.y * BN;
    const uint32_t sbase = smem_to_u32(smb);

    float acc[2][8][4];
#pragma unroll
    for (int i = 0; i < 2; i++)
#pragma unroll
        for (int j = 0; j < 8; j++)
#pragma unroll
            for (int v = 0; v < 4; v++) acc[i][j][v] = 0.f;

    auto issue_stage = [&](int s, int k0) {
        uint32_t dstb = sbase + s * (STAGE_ELEMS * 2);
#pragma unroll
        for (int i = 0; i < 8; i++) {
            int idx = i * 256 + tid;
            int mat = idx >> 9;
            int rem = idx & 511;
            int row = rem >> 2;
            int ch  = rem & 3;
            int grow = (mat < 2) ? (m0 + row) : (n0 + row);
            const __nv_bfloat16* base =
                (mat == 0) ? Ahi : (mat == 1) ? Alo : (mat == 2) ? Bhi : Blo;
            const __nv_bfloat16* src = base + (size_t)grow * K + k0 + ch * 8;
            uint32_t d = dstb + (uint32_t)(mat * MAT_ELEMS + row * PADK + ch * 8) * 2;
            cp_async16(d, src);
        }
    };

    // Hoisted per-thread ldsm offsets (within a stage)
    const uint32_t offA = (uint32_t)((wm * 32 + (lane & 15)) * PADK + (lane >> 4) * 8) * 2;
    const uint32_t offB = (uint32_t)(2 * MAT_ELEMS +
        (wn * 64 + (lane & 7) + ((lane >> 4) << 3)) * PADK + ((lane >> 3) & 1) * 8) * 2;

    issue_stage(0, 0);    cp_commit();
    issue_stage(1, BK);   cp_commit();

    const int nk = K / BK;
    for (int it = 0; it < nk; it++) {
        if (it + 1 < nk) cp_wait<1>();
        else             cp_wait<0>();
        __syncthreads();

        const uint32_t stb = sbase + (it & 1) * (STAGE_ELEMS * 2);
#pragma unroll
        for (int kk = 0; kk < 2; kk++) {
            uint32_t ah[2][4], al[2][4], bh[4][4], bl[4][4];
#pragma unroll
            for (int mt = 0; mt < 2; mt++) {
                uint32_t a = stb + offA + (uint32_t)(mt * 16 * PADK + kk * 16) * 2;
                ldsm4(ah[mt], a);
                ldsm4(al[mt], a + MAT_ELEMS * 2);
            }
#pragma unroll
            for (int nt = 0; nt < 4; nt++) {
                uint32_t a = stb + offB + (uint32_t)(nt * 16 * PADK + kk * 16) * 2;
                ldsm4(bh[nt], a);
                ldsm4(bl[nt], a + MAT_ELEMS * 2);
            }
            // pass 1: Ahi * Bhi over all 16 accumulators
#pragma unroll
            for (int mt = 0; mt < 2; mt++)
#pragma unroll
                for (int n8 = 0; n8 < 8; n8++)
                    mma_bf16(acc[mt][n8], ah[mt],
                             bh[n8 >> 1][(n8 & 1) * 2], bh[n8 >> 1][(n8 & 1) * 2 + 1]);
            // pass 2: Ahi * Blo
#pragma unroll
            for (int mt = 0; mt < 2; mt++)
#pragma unroll
                for (int n8 = 0; n8 < 8; n8++)
                    mma_bf16(acc[mt][n8], ah[mt],
                             bl[n8 >> 1][(n8 & 1) * 2], bl[n8 >> 1][(n8 & 1) * 2 + 1]);
            // pass 3: Alo * Bhi
#pragma unroll
            for (int mt = 0; mt < 2; mt++)
#pragma unroll
                for (int n8 = 0; n8 < 8; n8++)
                    mma_bf16(acc[mt][n8], al[mt],
                             bh[n8 >> 1][(n8 & 1) * 2], bh[n8 >> 1][(n8 & 1) * 2 + 1]);
        }
        __syncthreads();
        if (it + 2 < nk) {
            issue_stage(it & 1, (it + 2) * BK);
            cp_commit();
        }
    }

#pragma unroll
    for (int mt = 0; mt < 2; mt++) {
        int r0 = m0 + wm * 32 + mt * 16 + (lane >> 2);
#pragma unroll
        for (int n8 = 0; n8 < 8; n8++) {
            int col = n0 + wn * 64 + n8 * 8 + (lane & 3) * 2;
            *(float2*)(C + (size_t)r0 * Ntot + col) =
                make_float2(acc[mt][n8][0], acc[mt][n8][1]);
            *(float2*)(C + (size_t)(r0 + 8) * Ntot + col) =
                make_float2(acc[mt][n8][2], acc[mt][n8][3]);
        }
    }
}

// ===========================================================================
// fp32 -> bf16 hi/lo split; 8 elements per thread
// ===========================================================================
__global__ void split_bf16_kernel(const float* __restrict__ in,
                                  __nv_bfloat16* __restrict__ hi,
                                  __nv_bfloat16* __restrict__ lo, int n8)
{
    int i = blockIdx.x * blockDim.x + threadIdx.x;
    if (i >= n8) return;
    float4 va = *(const float4*)(in + (size_t)i * 8);
    float4 vb = *(const float4*)(in + (size_t)i * 8 + 4);
    float f[8] = {va.x, va.y, va.z, va.w, vb.x, vb.y, vb.z, vb.w};
    uint32_t hw[4], lw[4];
#pragma unroll
    for (int j = 0; j < 4; j++) {
        __nv_bfloat16 h0 = __float2bfloat16(f[2 * j]);
        __nv_bfloat16 h1 = __float2bfloat16(f[2 * j + 1]);
        __nv_bfloat162 hp = __nv_bfloat162(h0, h1);
        __nv_bfloat162 lp = __nv_bfloat162(
            __float2bfloat16(f[2 * j]     - __bfloat162float(h0)),
            __float2bfloat16(f[2 * j + 1] - __bfloat162float(h1)));
        hw[j] = *(uint32_t*)&hp;
        lw[j] = *(uint32_t*)&lp;
    }
    *(uint4*)(hi + (size_t)i * 8) = make_uint4(hw[0], hw[1], hw[2], hw[3]);
    *(uint4*)(lo + (size_t)i * 8) = make_uint4(lw[0], lw[1], lw[2], lw[3]);
}

// ===========================================================================
// RoPE + bf16 conversion, vectorized x4: q,k roped -> att_hi;
// v hi/lo split -> att_hi/att_lo.
// ===========================================================================
__global__ void rope_split_kernel(const float* __restrict__ qkv,
                                  const float* __restrict__ cs,
                                  const float* __restrict__ sn,
                                  __nv_bfloat16* __restrict__ ah,
                                  __nv_bfloat16* __restrict__ al)
{
    int idx = blockIdx.x * blockDim.x + threadIdx.x;
    const int total = M_ * NG_ * 6 * 16;
    if (idx >= total) return;

    int d4 = (idx & 15) * 4;
    int r = idx >> 4;
    int slot = r % 6; r /= 6;
    int g    = r % NG_; r /= NG_;
    int t = r & (T_ - 1);

    size_t off = (size_t)r * NQKV_ + g * 768 + slot * 128;
    const float* p = qkv + off;
    float4 x1 = *(const float4*)(p + d4);
    float4 x2 = *(const float4*)(p + d4 + 64);
    float o1[4], o2[4];

    if (slot < 5) {
        float4 c1 = *(const float4*)(cs + t * HS_ + d4);
        float4 s1 = *(const float4*)(sn + t * HS_ + d4);
        float4 c2 = *(const float4*)(cs + t * HS_ + d4 + 64);
        float4 s2 = *(const float4*)(sn + t * HS_ + d4 + 64);
        o1[0] = x1.x * c1.x - x2.x * s1.x;  o2[0] = x2.x * c2.x + x1.x * s2.x;
        o1[1] = x1.y * c1.y - x2.y * s1.y;  o2[1] = x2.y * c2.y + x1.y * s2.y;
        o1[2] = x1.z * c1.z - x2.z * s1.z;  o2[2] = x2.z * c2.z + x1.z * s2.z;
        o1[3] = x1.w * c1.w - x2.w * s1.w;  o2[3] = x2.w * c2.w + x1.w * s2.w;
        uint32_t w1[2], w2[2];
#pragma unroll
        for (int j = 0; j < 2; j++) {
            __nv_bfloat162 p1 = __nv_bfloat162(__float2bfloat16(o1[2 * j]),
                                               __float2bfloat16(o1[2 * j + 1]));
            __nv_bfloat162 p2 = __nv_bfloat162(__float2bfloat16(o2[2 * j]),
                                               __float2bfloat16(o2[2 * j + 1]));
            w1[j] = *(uint32_t*)&p1;
            w2[j] = *(uint32_t*)&p2;
        }
        *(uint2*)(ah + off + d4)      = make_uint2(w1[0], w1[1]);
        *(uint2*)(ah + off + d4 + 64) = make_uint2(w2[0], w2[1]);
    } else {
        float v[8] = {x1.x, x1.y, x1.z, x1.w, x2.x, x2.y, x2.z, x2.w};
        uint32_t hw[4], lw[4];
#pragma unroll
        for (int j = 0; j < 4; j++) {
            __nv_bfloat16 h0 = __float2bfloat16(v[2 * j]);
            __nv_bfloat16 h1 = __float2bfloat16(v[2 * j + 1]);
            __nv_bfloat162 hp = __nv_bfloat162(h0, h1);
            __nv_bfloat162 lp = __nv_bfloat162(
                __float2bfloat16(v[2 * j]     - __bfloat162float(h0)),
                __float2bfloat16(v[2 * j + 1] - __bfloat162float(h1)));
            hw[j] = *(uint32_t*)&hp;
            lw[j] = *(uint32_t*)&lp;
        }
        *(uint2*)(ah + off + d4)      = make_uint2(hw[0], hw[1]);
        *(uint2*)(ah + off + d4 + 64) = make_uint2(hw[2], hw[3]);
        *(uint2*)(al + off + d4)      = make_uint2(lw[0], lw[1]);
        *(uint2*)(al + off + d4 + 64) = make_uint2(lw[2], lw[3]);
    }
}

// ===========================================================================
// HMMA causal flash attention. 256 thr (8 warps), 128 q-rows/block,
// 64-key tiles double-buffered. QK bf16; PV split precision.
// Output bf16 hi/lo.
// ===========================================================================
#define AT_PAD 136
#define AT_TILE_E (64 * AT_PAD)
#define AT_Q_E (128 * AT_PAD)
#define ATT_SMEM ((AT_Q_E + 6 * AT_TILE_E) * 2)   // 139264 B

__global__ __launch_bounds__(256) void attn_hmma(
    const __nv_bfloat16* __restrict__ ah, const __nv_bfloat16* __restrict__ al,
    __nv_bfloat16* __restrict__ yhi, __nv_bfloat16* __restrict__ ylo)
{
    extern __shared__ __nv_bfloat16 smq[];
    const int tid  = threadIdx.x;
    const int wid  = tid >> 5;
    const int lane = tid & 31;
    const int qtb = gridDim.x - 1 - blockIdx.x;   // big blocks first
    const int bh = blockIdx.y;
    const int b = bh >> 5, h = bh & 31, g = h >> 2, qi = h & 3;
    const size_t rowbase = (size_t)b * T_ * NQKV_ + g * 768;
    const __nv_bfloat16* qb = ah + rowbase + qi * 128;
    const __nv_bfloat16* kb = ah + rowbase + 512;
    const __nv_bfloat16* vh = ah + rowbase + 640;
    const __nv_bfloat16* vl = al + rowbase + 640;
    const int q0 = qtb * 128;
    const int ntiles = 2 * qtb + 2;

    const uint32_t sb = smem_to_u32(smq);
    const uint32_t Qs = sb;
    uint32_t St[2];
    St[0] = sb + AT_Q_E * 2;
    St[1] = St[0] + 3 * AT_TILE_E * 2;

    // Q tile: 128 rows x 16 chunks
#pragma unroll
    for (int i = 0; i < 8; i++) {
        int idx = i * 256 + tid;
        int row = idx >> 4, ch = idx & 15;
        cp_async16(Qs + (uint32_t)(row * AT_PAD + ch * 8) * 2,
                   qb + (size_t)(q0 + row) * NQKV_ + ch * 8);
    }

    auto issue_kv = [&](int st, int k0) {
        uint32_t base = St[st];
#pragma unroll
        for (int i = 0; i < 12; i++) {
            int idx = i * 256 + tid;
            int arr = idx >> 10;
            int rem = idx & 1023;
            int row = rem >> 4, ch = rem & 15;
            const __nv_bfloat16* src =
                (arr == 0 ? kb : arr == 1 ? vh : vl) + (size_t)(k0 + row) * NQKV_ + ch * 8;
            cp_async16(base + (uint32_t)(arr * AT_TILE_E + row * AT_PAD + ch * 8) * 2, src);
        }
    };
    issue_kv(0, 0);
    cp_commit();

    float m_[2] = {-1e30f, -1e30f}, l_[2] = {0.f, 0.f};
    float O[16][4];
#pragma unroll
    for (int n = 0; n < 16; n++)
#pragma unroll
        for (int v = 0; v < 4; v++) O[n][v] = 0.f;

    const float sc = 0.08838834764831845f;
    const int r1 = lane >> 2;
    const int qw = q0 + wid * 16;            // warp's first q row (global)

    for (int kt = 0; kt < ntiles; kt++) {
        const int st = kt & 1;
        const int k0 = kt * 64;
        if (kt + 1 < ntiles) {
            issue_kv(st ^ 1, (kt + 1) * 64);
            cp_commit();
            cp_wait<1>();
        } else {
            cp_wait<0>();
        }
        __syncthreads();

        const uint32_t Ks  = St[st];
        const uint32_t Vhs = St[st] + AT_TILE_E * 2;
        const uint32_t Vls = Vhs + AT_TILE_E * 2;

        // ---- S = Q K^T ----
        float s[8][4];
#pragma unroll
        for (int j = 0; j < 8; j++)
#pragma unroll
            for (int v = 0; v < 4; v++) s[j][v] = 0.f;

#pragma unroll
        for (int t = 0; t < 8; t++) {
            uint32_t a[4];
            ldsm4(a, Qs + (uint32_t)((wid * 16 + (lane & 15)) * AT_PAD +
                                     t * 16 + (lane >> 4) * 8) * 2);
#pragma unroll
            for (int u = 0; u < 4; u++) {
                uint32_t bb[4];
                ldsm4(bb, Ks + (uint32_t)((u * 16 + ((lane >> 4) << 3) + (lane & 7)) * AT_PAD +
                                          t * 16 + ((lane >> 3) & 1) * 8) * 2);
                mma_bf16(s[2 * u],     a, bb[0], bb[1]);
                mma_bf16(s[2 * u + 1], a, bb[2], bb[3]);
            }
        }

#pragma unroll
        for (int j = 0; j < 8; j++)
#pragma unroll
            for (int v = 0; v < 4; v++) s[j][v] *= sc;

        if (k0 + 63 > qw) {   // tile touches/exceeds this warp's causal boundary
#pragma unroll
            for (int j = 0; j < 8; j++)
#pragma unroll
                for (int v = 0; v < 4; v++) {
                    int key = k0 + j * 8 + (lane & 3) * 2 + (v & 1);
                    int qr  = qw + r1 + ((v >> 1) << 3);
                    if (key > qr) s[j][v] = -1e30f;
                }
        }

        // ---- online softmax ----
#pragma unroll
        for (int rr = 0; rr < 2; rr++) {
            float mx = -1e30f;
#pragma unroll
            for (int j = 0; j < 8; j++) {
                mx = fmaxf(mx, s[j][rr * 2]);
                mx = fmaxf(mx, s[j][rr * 2 + 1]);
            }
            mx = fmaxf(mx, __shfl_xor_sync(0xffffffffu, mx, 1));
            mx = fmaxf(mx, __shfl_xor_sync(0xffffffffu, mx, 2));
            float mnew = fmaxf(m_[rr], mx);
            float corr = __expf(m_[rr] - mnew);
            float sum = 0.f;
#pragma unroll
            for (int j = 0; j < 8; j++) {
                float p0 = __expf(s[j][rr * 2]     - mnew);
                float p1 = __expf(s[j][rr * 2 + 1] - mnew);
                s[j][rr * 2]     = p0;
                s[j][rr * 2 + 1] = p1;
                sum += p0 + p1;
            }
            sum += __shfl_xor_sync(0xffffffffu, sum, 1);
            sum += __shfl_xor_sync(0xffffffffu, sum, 2);
            l_[rr] = l_[rr] * corr + sum;
            m_[rr] = mnew;
#pragma unroll
            for (int n = 0; n < 16; n++) {
                O[n][rr * 2]     *= corr;
                O[n][rr * 2 + 1] *= corr;
            }
        }

        // ---- O += P V (split precision) ----
#pragma unroll
        for (int t = 0; t < 4; t++) {
            uint32_t phi[4], plo[4];
#pragma unroll
            for (int v = 0; v < 2; v++) {
                float p0 = s[2 * t][v * 2], p1 = s[2 * t][v * 2 + 1];
                float p2 = s[2 * t + 1][v * 2], p3 = s[2 * t + 1][v * 2 + 1];
                __nv_bfloat16 h0 = __float2bfloat16(p0), h1 = __float2bfloat16(p1);
                __nv_bfloat16 h2 = __float2bfloat16(p2), h3 = __float2bfloat16(p3);
                __nv_bfloat162 hp0 = __nv_bfloat162(h0, h1);
                __nv_bfloat162 hp1 = __nv_bfloat162(h2, h3);
                phi[v]     = *(uint32_t*)&hp0;
                phi[v + 2] = *(uint32_t*)&hp1;
                __nv_bfloat162 lp0 = __nv_bfloat162(
                    __float2bfloat16(p0 - __bfloat162float(h0)),
                    __float2bfloat16(p1 - __bfloat162float(h1)));
                __nv_bfloat162 lp1 = __nv_bfloat162(
                    __float2bfloat16(p2 - __bfloat162float(h2)),
                    __float2bfloat16(p3 - __bfloat162float(h3)));
                plo[v]     = *(uint32_t*)&lp0;
                plo[v + 2] = *(uint32_t*)&lp1;
            }
#pragma unroll
            for (int dg = 0; dg < 8; dg++) {
                uint32_t roff = (uint32_t)((t * 16 + ((lane >> 3) & 1) * 8 + (lane & 7)) * AT_PAD +
                                           dg * 16 + (lane >> 4) * 8) * 2;
                uint32_t bhv[4], blv[4];
                ldsm4t(bhv, Vhs + roff);
                ldsm4t(blv, Vls + roff);
                mma_bf16(O[2 * dg],     phi, bhv[0], bhv[1]);
                mma_bf16(O[2 * dg + 1], phi, bhv[2], bhv[3]);
                mma_bf16(O[2 * dg],     phi, blv[0], blv[1]);
                mma_bf16(O[2 * dg + 1], phi, blv[2], blv[3]);
                mma_bf16(O[2 * dg],     plo, bhv[0], bhv[1]);
                mma_bf16(O[2 * dg + 1], plo, bhv[2], bhv[3]);
            }
        }
        __syncthreads();
    }

    // Epilogue: normalize, write bf16 hi/lo
#pragma unroll
    for (int rr = 0; rr < 2; rr++) {
        float inv = 1.f / l_[rr];
        int row = qw + r1 + rr * 8;
        size_t rb = (size_t)(b * T_ + row) * C_ + h * 128;
#pragma unroll
        for (int n = 0; n < 16; n++) {
            int col = n * 8 + (lane & 3) * 2;
            float o0 = O[n][rr * 2] * inv;
            float o1 = O[n][rr * 2 + 1] * inv;
            __nv_bfloat16 h0 = __float2bfloat16(o0);
            __nv_bfloat16 h1 = __float2bfloat16(o1);
            __nv_bfloat162 hp = __nv_bfloat162(h0, h1);
            __nv_bfloat162 lp = __nv_bfloat162(
                __float2bfloat16(o0 - __bfloat162float(h0)),
                __float2bfloat16(o1 - __bfloat162float(h1)));
            *(uint32_t*)(yhi + rb + col) = *(uint32_t*)&hp;
            *(uint32_t*)(ylo + rb + col) = *(uint32_t*)&lp;
        }
    }
}

// ===========================================================================
// Launch
// ===========================================================================
extern "C" void kernel_launch(void* const* d_in, const int* in_sizes, int n_in,
                              void* d_out, int out_size)
{
    const float* x     = (const float*)d_in[0];
    const float* cosb  = (const float*)d_in[1];
    const float* sinb  = (const float*)d_in[2];
    const float* Wqkv  = (const float*)d_in[3];
    const float* Wproj = (const float*)d_in[4];
    float* out = (float*)d_out;

    float* qkv = nullptr;
    __nv_bfloat16 *atth, *attl, *ahi, *alo, *bhi, *blo;
    cudaGetSymbolAddress((void**)&qkv,  g_qkv);
    cudaGetSymbolAddress((void**)&atth, g_att_hi);
    cudaGetSymbolAddress((void**)&attl, g_att_lo);
    cudaGetSymbolAddress((void**)&ahi,  g_a_hi);
    cudaGetSymbolAddress((void**)&alo,  g_a_lo);
    cudaGetSymbolAddress((void**)&bhi,  g_b_hi);
    cudaGetSymbolAddress((void**)&blo,  g_b_lo);

    cudaFuncSetAttribute(hmma_gemm, cudaFuncAttributeMaxDynamicSharedMemorySize,
                         GEMM_SMEM);
    cudaFuncSetAttribute(attn_hmma, cudaFuncAttributeMaxDynamicSharedMemorySize,
                         ATT_SMEM);

    // ---- GEMM 1: qkv = x @ Wqkv^T ----
    {
        int n8a = M_ * C_ / 8, n8b = NQKV_ * C_ / 8;
        split_bf16_kernel<<<(n8a + 255) / 256, 256>>>(x, ahi, alo, n8a);
        split_bf16_kernel<<<(n8b + 255) / 256, 256>>>(Wqkv, bhi, blo, n8b);
        hmma_gemm<<<dim3(M_ / BM, NQKV_ / BN), 256, GEMM_SMEM>>>(
            ahi, alo, bhi, blo, qkv, NQKV_, C_);
    }

    // ---- RoPE + bf16 conversion ----
    {
        int total = M_ * NG_ * 6 * 16;
        rope_split_kernel<<<(total + 255) / 256, 256>>>(qkv, cosb, sinb, atth, attl);
    }

    // ---- HMMA attention -> y (bf16 hi/lo into GEMM2 A buffers) ----
    attn_hmma<<<dim3(T_ / 128, B_ * NH_), 256, ATT_SMEM>>>(atth, attl, ahi, alo);

    // ---- GEMM 2: out = y @ Wproj^T ----
    {
        int n8b = C_ * C_ / 8;
        split_bf16_kernel<<<(n8b + 255) / 256, 256>>>(Wproj, bhi, blo, n8b);
        hmma_gemm<<<dim3(M_ / BM, C_ / BN), 256, GEMM_SMEM>>>(
            ahi, alo, bhi, blo, out, C_, C_);
    }
}

// round 8
// speedup vs baseline: 4.3449x; 1.3251x over previous
#include <cuda_runtime.h>
#include <cuda_bf16.h>
#include <cuda_fp16.h>
#include <math.h>
#include <stdint.h>

// Problem constants
#define B_    2
#define T_    2048
#define C_    4096
#define NH_   32
#define NG_   8
#define HS_   128
#define M_    (B_ * T_)                 // 4096 rows
#define NQKV_ ((NH_ + 2 * NG_) * HS_)   // 6144

// Scratch (no cudaMalloc allowed)
__device__ float g_qkv[(size_t)M_ * NQKV_];               // 100.7 MB fp32 qkv
__device__ __nv_bfloat16 g_att_hi[(size_t)M_ * NQKV_];    // 50 MB (attention in)
__device__ __nv_bfloat16 g_att_lo[(size_t)M_ * NQKV_];    // 50 MB (v lo)
__device__ __half g_a_hi[(size_t)M_ * C_];                // 32 MB (x hi / y hi, fp16)
__device__ __half g_b_hi[(size_t)NQKV_ * C_];             // 48 MB (W hi, fp16)
__device__ __half g_b_lo[(size_t)NQKV_ * C_];             // 48 MB (W lo, fp16)

// ===========================================================================
// PTX helpers
// ===========================================================================
__device__ __forceinline__ uint32_t smem_to_u32(const void* p) {
    uint32_t a;
    asm("{ .reg .u64 t; cvta.to.shared.u64 t, %1; cvt.u32.u64 %0, t; }"
        : "=r"(a) : "l"(p));
    return a;
}
__device__ __forceinline__ void cp_async16(uint32_t dst, const void* src) {
    asm volatile("cp.async.cg.shared.global [%0], [%1], 16;" :: "r"(dst), "l"(src));
}
__device__ __forceinline__ void cp_commit() {
    asm volatile("cp.async.commit_group;");
}
template <int N> __device__ __forceinline__ void cp_wait() {
    asm volatile("cp.async.wait_group %0;" :: "n"(N));
}
__device__ __forceinline__ void ldsm4(uint32_t* r, uint32_t addr) {
    asm volatile("ldmatrix.sync.aligned.m8n8.x4.shared.b16 {%0,%1,%2,%3}, [%4];"
        : "=r"(r[0]), "=r"(r[1]), "=r"(r[2]), "=r"(r[3]) : "r"(addr));
}
__device__ __forceinline__ void ldsm4t(uint32_t* r, uint32_t addr) {
    asm volatile("ldmatrix.sync.aligned.m8n8.x4.trans.shared.b16 {%0,%1,%2,%3}, [%4];"
        : "=r"(r[0]), "=r"(r[1]), "=r"(r[2]), "=r"(r[3]) : "r"(addr));
}
__device__ __forceinline__ void mma_bf16(float* d, const uint32_t* a,
                                         uint32_t b0, uint32_t b1) {
    asm volatile(
        "mma.sync.aligned.m16n8k16.row.col.f32.bf16.bf16.f32 "
        "{%0,%1,%2,%3}, {%4,%5,%6,%7}, {%8,%9}, {%0,%1,%2,%3};"
        : "+f"(d[0]), "+f"(d[1]), "+f"(d[2]), "+f"(d[3])
        : "r"(a[0]), "r"(a[1]), "r"(a[2]), "r"(a[3]), "r"(b0), "r"(b1));
}
__device__ __forceinline__ void mma_f16(float* d, const uint32_t* a,
                                        uint32_t b0, uint32_t b1) {
    asm volatile(
        "mma.sync.aligned.m16n8k16.row.col.f32.f16.f16.f32 "
        "{%0,%1,%2,%3}, {%4,%5,%6,%7}, {%8,%9}, {%0,%1,%2,%3};"
        : "+f"(d[0]), "+f"(d[1]), "+f"(d[2]), "+f"(d[3])
        : "r"(a[0]), "r"(a[1]), "r"(a[2]), "r"(a[3]), "r"(b0), "r"(b1));
}

// ===========================================================================
// fp16 2-pass HMMA GEMM: C = Ahi@Bhi^T + Ahi@Blo^T  (A fp16-hi; B fp16 hi/lo)
// 128x128x32 tiles, 256 threads (8 warps 4x2), 2-stage double buffer,
// 3 matrices/stage (61.5KB) -> 2 CTAs/SM.
// ===========================================================================
#define BM 128
#define BN 128
#define BK 32
#define PADK 40
#define MAT_ELEMS (128 * PADK)            // 5120 halves
#define STAGE_ELEMS (3 * MAT_ELEMS)       // 15360 halves
#define NSTAGE 2
#define GEMM_SMEM (NSTAGE * STAGE_ELEMS * 2)   // 61440 B

__global__ __launch_bounds__(256, 2) void hmma_gemm(
    const __half* __restrict__ Ahi,
    const __half* __restrict__ Bhi, const __half* __restrict__ Blo,
    float* __restrict__ C, int Ntot, int K)
{
    extern __shared__ __half smb[];
    const int tid  = threadIdx.x;
    const int wid  = tid >> 5;
    const int lane = tid & 31;
    const int wm   = wid & 3;
    const int wn   = wid >> 2;
    const int m0   = blockIdx.x * BM;
    const int n0   = blockIdx.y * BN;
    const uint32_t sbase = smem_to_u32(smb);

    float acc[2][8][4];
#pragma unroll
    for (int i = 0; i < 2; i++)
#pragma unroll
        for (int j = 0; j < 8; j++)
#pragma unroll
            for (int v = 0; v < 4; v++) acc[i][j][v] = 0.f;

    auto issue_stage = [&](int s, int k0) {
        uint32_t dstb = sbase + s * (STAGE_ELEMS * 2);
#pragma unroll
        for (int i = 0; i < 6; i++) {
            int idx = i * 256 + tid;
            int mat = idx >> 9;              // 0=Ahi 1=Bhi 2=Blo
            int rem = idx & 511;
            int row = rem >> 2;
            int ch  = rem & 3;
            int grow = (mat == 0) ? (m0 + row) : (n0 + row);
            const __half* base = (mat == 0) ? Ahi : (mat == 1) ? Bhi : Blo;
            const __half* src = base + (size_t)grow * K + k0 + ch * 8;
            uint32_t d = dstb + (uint32_t)(mat * MAT_ELEMS + row * PADK + ch * 8) * 2;
            cp_async16(d, src);
        }
    };

    // Hoisted per-thread ldsm offsets (within a stage)
    const uint32_t offA = (uint32_t)((wm * 32 + (lane & 15)) * PADK + (lane >> 4) * 8) * 2;
    const uint32_t offB = (uint32_t)(MAT_ELEMS +
        (wn * 64 + (lane & 7) + ((lane >> 4) << 3)) * PADK + ((lane >> 3) & 1) * 8) * 2;

    issue_stage(0, 0);    cp_commit();
    issue_stage(1, BK);   cp_commit();

    const int nk = K / BK;
    for (int it = 0; it < nk; it++) {
        if (it + 1 < nk) cp_wait<1>();
        else             cp_wait<0>();
        __syncthreads();

        const uint32_t stb = sbase + (it & 1) * (STAGE_ELEMS * 2);
#pragma unroll
        for (int kk = 0; kk < 2; kk++) {
            uint32_t ah[2][4], bh[4][4], bl[4][4];
#pragma unroll
            for (int mt = 0; mt < 2; mt++) {
                uint32_t a = stb + offA + (uint32_t)(mt * 16 * PADK + kk * 16) * 2;
                ldsm4(ah[mt], a);
            }
#pragma unroll
            for (int nt = 0; nt < 4; nt++) {
                uint32_t a = stb + offB + (uint32_t)(nt * 16 * PADK + kk * 16) * 2;
                ldsm4(bh[nt], a);
                ldsm4(bl[nt], a + MAT_ELEMS * 2);
            }
            // pass 1: Ahi * Bhi
#pragma unroll
            for (int mt = 0; mt < 2; mt++)
#pragma unroll
                for (int n8 = 0; n8 < 8; n8++)
                    mma_f16(acc[mt][n8], ah[mt],
                            bh[n8 >> 1][(n8 & 1) * 2], bh[n8 >> 1][(n8 & 1) * 2 + 1]);
            // pass 2: Ahi * Blo
#pragma unroll
            for (int mt = 0; mt < 2; mt++)
#pragma unroll
                for (int n8 = 0; n8 < 8; n8++)
                    mma_f16(acc[mt][n8], ah[mt],
                            bl[n8 >> 1][(n8 & 1) * 2], bl[n8 >> 1][(n8 & 1) * 2 + 1]);
        }
        __syncthreads();
        if (it + 2 < nk) {
            issue_stage(it & 1, (it + 2) * BK);
            cp_commit();
        }
    }

#pragma unroll
    for (int mt = 0; mt < 2; mt++) {
        int r0 = m0 + wm * 32 + mt * 16 + (lane >> 2);
#pragma unroll
        for (int n8 = 0; n8 < 8; n8++) {
            int col = n0 + wn * 64 + n8 * 8 + (lane & 3) * 2;
            *(float2*)(C + (size_t)r0 * Ntot + col) =
                make_float2(acc[mt][n8][0], acc[mt][n8][1]);
            *(float2*)(C + (size_t)(r0 + 8) * Ntot + col) =
                make_float2(acc[mt][n8][2], acc[mt][n8][3]);
        }
    }
}

// ===========================================================================
// fp32 -> fp16 hi/lo split (weights); 8 elements per thread
// ===========================================================================
__global__ void split_f16_kernel(const float* __restrict__ in,
                                 __half* __restrict__ hi,
                                 __half* __restrict__ lo, int n8)
{
    int i = blockIdx.x * blockDim.x + threadIdx.x;
    if (i >= n8) return;
    float4 va = *(const float4*)(in + (size_t)i * 8);
    float4 vb = *(const float4*)(in + (size_t)i * 8 + 4);
    float f[8] = {va.x, va.y, va.z, va.w, vb.x, vb.y, vb.z, vb.w};
    uint32_t hw[4], lw[4];
#pragma unroll
    for (int j = 0; j < 4; j++) {
        __half h0 = __float2half_rn(f[2 * j]);
        __half h1 = __float2half_rn(f[2 * j + 1]);
        __half2 hp = __halves2half2(h0, h1);
        __half2 lp = __halves2half2(
            __float2half_rn(f[2 * j]     - __half2float(h0)),
            __float2half_rn(f[2 * j + 1] - __half2float(h1)));
        hw[j] = *(uint32_t*)&hp;
        lw[j] = *(uint32_t*)&lp;
    }
    *(uint4*)(hi + (size_t)i * 8) = make_uint4(hw[0], hw[1], hw[2], hw[3]);
    *(uint4*)(lo + (size_t)i * 8) = make_uint4(lw[0], lw[1], lw[2], lw[3]);
}

// fp32 -> fp16 hi only (activations); 8 elements per thread
__global__ void convert_f16_kernel(const float* __restrict__ in,
                                   __half* __restrict__ hi, int n8)
{
    int i = blockIdx.x * blockDim.x + threadIdx.x;
    if (i >= n8) return;
    float4 va = *(const float4*)(in + (size_t)i * 8);
    float4 vb = *(const float4*)(in + (size_t)i * 8 + 4);
    __half2 h0 = __floats2half2_rn(va.x, va.y);
    __half2 h1 = __floats2half2_rn(va.z, va.w);
    __half2 h2 = __floats2half2_rn(vb.x, vb.y);
    __half2 h3 = __floats2half2_rn(vb.z, vb.w);
    *(uint4*)(hi + (size_t)i * 8) = make_uint4(
        *(uint32_t*)&h0, *(uint32_t*)&h1, *(uint32_t*)&h2, *(uint32_t*)&h3);
}

// ===========================================================================
// RoPE + bf16 conversion, vectorized x4: q,k roped -> att_hi;
// v hi/lo split -> att_hi/att_lo.   (attention stays bf16-split)
// ===========================================================================
__global__ void rope_split_kernel(const float* __restrict__ qkv,
                                  const float* __restrict__ cs,
                                  const float* __restrict__ sn,
                                  __nv_bfloat16* __restrict__ ah,
                                  __nv_bfloat16* __restrict__ al)
{
    int idx = blockIdx.x * blockDim.x + threadIdx.x;
    const int total = M_ * NG_ * 6 * 16;
    if (idx >= total) return;

    int d4 = (idx & 15) * 4;
    int r = idx >> 4;
    int slot = r % 6; r /= 6;
    int g    = r % NG_; r /= NG_;
    int t = r & (T_ - 1);

    size_t off = (size_t)r * NQKV_ + g * 768 + slot * 128;
    const float* p = qkv + off;
    float4 x1 = *(const float4*)(p + d4);
    float4 x2 = *(const float4*)(p + d4 + 64);
    float o1[4], o2[4];

    if (slot < 5) {
        float4 c1 = *(const float4*)(cs + t * HS_ + d4);
        float4 s1 = *(const float4*)(sn + t * HS_ + d4);
        float4 c2 = *(const float4*)(cs + t * HS_ + d4 + 64);
        float4 s2 = *(const float4*)(sn + t * HS_ + d4 + 64);
        o1[0] = x1.x * c1.x - x2.x * s1.x;  o2[0] = x2.x * c2.x + x1.x * s2.x;
        o1[1] = x1.y * c1.y - x2.y * s1.y;  o2[1] = x2.y * c2.y + x1.y * s2.y;
        o1[2] = x1.z * c1.z - x2.z * s1.z;  o2[2] = x2.z * c2.z + x1.z * s2.z;
        o1[3] = x1.w * c1.w - x2.w * s1.w;  o2[3] = x2.w * c2.w + x1.w * s2.w;
        uint32_t w1[2], w2[2];
#pragma unroll
        for (int j = 0; j < 2; j++) {
            __nv_bfloat162 p1 = __nv_bfloat162(__float2bfloat16(o1[2 * j]),
                                               __float2bfloat16(o1[2 * j + 1]));
            __nv_bfloat162 p2 = __nv_bfloat162(__float2bfloat16(o2[2 * j]),
                                               __float2bfloat16(o2[2 * j + 1]));
            w1[j] = *(uint32_t*)&p1;
            w2[j] = *(uint32_t*)&p2;
        }
        *(uint2*)(ah + off + d4)      = make_uint2(w1[0], w1[1]);
        *(uint2*)(ah + off + d4 + 64) = make_uint2(w2[0], w2[1]);
    } else {
        float v[8] = {x1.x, x1.y, x1.z, x1.w, x2.x, x2.y, x2.z, x2.w};
        uint32_t hw[4], lw[4];
#pragma unroll
        for (int j = 0; j < 4; j++) {
            __nv_bfloat16 h0 = __float2bfloat16(v[2 * j]);
            __nv_bfloat16 h1 = __float2bfloat16(v[2 * j + 1]);
            __nv_bfloat162 hp = __nv_bfloat162(h0, h1);
            __nv_bfloat162 lp = __nv_bfloat162(
                __float2bfloat16(v[2 * j]     - __bfloat162float(h0)),
                __float2bfloat16(v[2 * j + 1] - __bfloat162float(h1)));
            hw[j] = *(uint32_t*)&hp;
            lw[j] = *(uint32_t*)&lp;
        }
        *(uint2*)(ah + off + d4)      = make_uint2(hw[0], hw[1]);
        *(uint2*)(ah + off + d4 + 64) = make_uint2(hw[2], hw[3]);
        *(uint2*)(al + off + d4)      = make_uint2(lw[0], lw[1]);
        *(uint2*)(al + off + d4 + 64) = make_uint2(lw[2], lw[3]);
    }
}

// ===========================================================================
// HMMA causal flash attention (bf16 QK, split-precision PV).
// 256 thr (8 warps), 128 q-rows/block, 64-key tiles double-buffered.
// Output y written as fp16 (hi only) for the fp16 2-pass GEMM2.
// ===========================================================================
#define AT_PAD 136
#define AT_TILE_E (64 * AT_PAD)
#define AT_Q_E (128 * AT_PAD)
#define ATT_SMEM ((AT_Q_E + 6 * AT_TILE_E) * 2)   // 139264 B

__global__ __launch_bounds__(256) void attn_hmma(
    const __nv_bfloat16* __restrict__ ah, const __nv_bfloat16* __restrict__ al,
    __half* __restrict__ yhi)
{
    extern __shared__ __nv_bfloat16 smq[];
    const int tid  = threadIdx.x;
    const int wid  = tid >> 5;
    const int lane = tid & 31;
    const int qtb = gridDim.x - 1 - blockIdx.x;   // big blocks first
    const int bh = blockIdx.y;
    const int b = bh >> 5, h = bh & 31, g = h >> 2, qi = h & 3;
    const size_t rowbase = (size_t)b * T_ * NQKV_ + g * 768;
    const __nv_bfloat16* qb = ah + rowbase + qi * 128;
    const __nv_bfloat16* kb = ah + rowbase + 512;
    const __nv_bfloat16* vh = ah + rowbase + 640;
    const __nv_bfloat16* vl = al + rowbase + 640;
    const int q0 = qtb * 128;
    const int ntiles = 2 * qtb + 2;

    const uint32_t sb = smem_to_u32(smq);
    const uint32_t Qs = sb;
    uint32_t St[2];
    St[0] = sb + AT_Q_E * 2;
    St[1] = St[0] + 3 * AT_TILE_E * 2;

    // Q tile: 128 rows x 16 chunks
#pragma unroll
    for (int i = 0; i < 8; i++) {
        int idx = i * 256 + tid;
        int row = idx >> 4, ch = idx & 15;
        cp_async16(Qs + (uint32_t)(row * AT_PAD + ch * 8) * 2,
                   qb + (size_t)(q0 + row) * NQKV_ + ch * 8);
    }

    auto issue_kv = [&](int st, int k0) {
        uint32_t base = St[st];
#pragma unroll
        for (int i = 0; i < 12; i++) {
            int idx = i * 256 + tid;
            int arr = idx >> 10;
            int rem = idx & 1023;
            int row = rem >> 4, ch = rem & 15;
            const __nv_bfloat16* src =
                (arr == 0 ? kb : arr == 1 ? vh : vl) + (size_t)(k0 + row) * NQKV_ + ch * 8;
            cp_async16(base + (uint32_t)(arr * AT_TILE_E + row * AT_PAD + ch * 8) * 2, src);
        }
    };
    issue_kv(0, 0);
    cp_commit();

    float m_[2] = {-1e30f, -1e30f}, l_[2] = {0.f, 0.f};
    float O[16][4];
#pragma unroll
    for (int n = 0; n < 16; n++)
#pragma unroll
        for (int v = 0; v < 4; v++) O[n][v] = 0.f;

    const float sc = 0.08838834764831845f;
    const int r1 = lane >> 2;
    const int qw = q0 + wid * 16;            // warp's first q row (global)

    for (int kt = 0; kt < ntiles; kt++) {
        const int st = kt & 1;
        const int k0 = kt * 64;
        if (kt + 1 < ntiles) {
            issue_kv(st ^ 1, (kt + 1) * 64);
            cp_commit();
            cp_wait<1>();
        } else {
            cp_wait<0>();
        }
        __syncthreads();

        const uint32_t Ks  = St[st];
        const uint32_t Vhs = St[st] + AT_TILE_E * 2;
        const uint32_t Vls = Vhs + AT_TILE_E * 2;

        // ---- S = Q K^T ----
        float s[8][4];
#pragma unroll
        for (int j = 0; j < 8; j++)
#pragma unroll
            for (int v = 0; v < 4; v++) s[j][v] = 0.f;

#pragma unroll
        for (int t = 0; t < 8; t++) {
            uint32_t a[4];
            ldsm4(a, Qs + (uint32_t)((wid * 16 + (lane & 15)) * AT_PAD +
                                     t * 16 + (lane >> 4) * 8) * 2);
#pragma unroll
            for (int u = 0; u < 4; u++) {
                uint32_t bb[4];
                ldsm4(bb, Ks + (uint32_t)((u * 16 + ((lane >> 4) << 3) + (lane & 7)) * AT_PAD +
                                          t * 16 + ((lane >> 3) & 1) * 8) * 2);
                mma_bf16(s[2 * u],     a, bb[0], bb[1]);
                mma_bf16(s[2 * u + 1], a, bb[2], bb[3]);
            }
        }

#pragma unroll
        for (int j = 0; j < 8; j++)
#pragma unroll
            for (int v = 0; v < 4; v++) s[j][v] *= sc;

        if (k0 + 63 > qw) {   // tile touches/exceeds this warp's causal boundary
#pragma unroll
            for (int j = 0; j < 8; j++)
#pragma unroll
                for (int v = 0; v < 4; v++) {
                    int key = k0 + j * 8 + (lane & 3) * 2 + (v & 1);
                    int qr  = qw + r1 + ((v >> 1) << 3);
                    if (key > qr) s[j][v] = -1e30f;
                }
        }

        // ---- online softmax ----
#pragma unroll
        for (int rr = 0; rr < 2; rr++) {
            float mx = -1e30f;
#pragma unroll
            for (int j = 0; j < 8; j++) {
                mx = fmaxf(mx, s[j][rr * 2]);
                mx = fmaxf(mx, s[j][rr * 2 + 1]);
            }
            mx = fmaxf(mx, __shfl_xor_sync(0xffffffffu, mx, 1));
            mx = fmaxf(mx, __shfl_xor_sync(0xffffffffu, mx, 2));
            float mnew = fmaxf(m_[rr], mx);
            float corr = __expf(m_[rr] - mnew);
            float sum = 0.f;
#pragma unroll
            for (int j = 0; j < 8; j++) {
                float p0 = __expf(s[j][rr * 2]     - mnew);
                float p1 = __expf(s[j][rr * 2 + 1] - mnew);
                s[j][rr * 2]     = p0;
                s[j][rr * 2 + 1] = p1;
                sum += p0 + p1;
            }
            sum += __shfl_xor_sync(0xffffffffu, sum, 1);
            sum += __shfl_xor_sync(0xffffffffu, sum, 2);
            l_[rr] = l_[rr] * corr + sum;
            m_[rr] = mnew;
#pragma unroll
            for (int n = 0; n < 16; n++) {
                O[n][rr * 2]     *= corr;
                O[n][rr * 2 + 1] *= corr;
            }
        }

        // ---- O += P V (split precision) ----
#pragma unroll
        for (int t = 0; t < 4; t++) {
            uint32_t phi[4], plo[4];
#pragma unroll
            for (int v = 0; v < 2; v++) {
                float p0 = s[2 * t][v * 2], p1 = s[2 * t][v * 2 + 1];
                float p2 = s[2 * t + 1][v * 2], p3 = s[2 * t + 1][v * 2 + 1];
                __nv_bfloat16 h0 = __float2bfloat16(p0), h1 = __float2bfloat16(p1);
                __nv_bfloat16 h2 = __float2bfloat16(p2), h3 = __float2bfloat16(p3);
                __nv_bfloat162 hp0 = __nv_bfloat162(h0, h1);
                __nv_bfloat162 hp1 = __nv_bfloat162(h2, h3);
                phi[v]     = *(uint32_t*)&hp0;
                phi[v + 2] = *(uint32_t*)&hp1;
                __nv_bfloat162 lp0 = __nv_bfloat162(
                    __float2bfloat16(p0 - __bfloat162float(h0)),
                    __float2bfloat16(p1 - __bfloat162float(h1)));
                __nv_bfloat162 lp1 = __nv_bfloat162(
                    __float2bfloat16(p2 - __bfloat162float(h2)),
                    __float2bfloat16(p3 - __bfloat162float(h3)));
                plo[v]     = *(uint32_t*)&lp0;
                plo[v + 2] = *(uint32_t*)&lp1;
            }
#pragma unroll
            for (int dg = 0; dg < 8; dg++) {
                uint32_t roff = (uint32_t)((t * 16 + ((lane >> 3) & 1) * 8 + (lane & 7)) * AT_PAD +
                                           dg * 16 + (lane >> 4) * 8) * 2;
                uint32_t bhv[4], blv[4];
                ldsm4t(bhv, Vhs + roff);
                ldsm4t(blv, Vls + roff);
                mma_bf16(O[2 * dg],     phi, bhv[0], bhv[1]);
                mma_bf16(O[2 * dg + 1], phi, bhv[2], bhv[3]);
                mma_bf16(O[2 * dg],     phi, blv[0], blv[1]);
                mma_bf16(O[2 * dg + 1], phi, blv[2], blv[3]);
                mma_bf16(O[2 * dg],     plo, bhv[0], bhv[1]);
                mma_bf16(O[2 * dg + 1], plo, bhv[2], bhv[3]);
            }
        }
        __syncthreads();
    }

    // Epilogue: normalize, write y as fp16 (hi only)
#pragma unroll
    for (int rr = 0; rr < 2; rr++) {
        float inv = 1.f / l_[rr];
        int row = qw + r1 + rr * 8;
        size_t rb = (size_t)(b * T_ + row) * C_ + h * 128;
#pragma unroll
        for (int n = 0; n < 16; n++) {
            int col = n * 8 + (lane & 3) * 2;
            __half2 hp = __floats2half2_rn(O[n][rr * 2] * inv,
                                           O[n][rr * 2 + 1] * inv);
            *(uint32_t*)(yhi + rb + col) = *(uint32_t*)&hp;
        }
    }
}

// ===========================================================================
// Launch
// ===========================================================================
extern "C" void kernel_launch(void* const* d_in, const int* in_sizes, int n_in,
                              void* d_out, int out_size)
{
    const float* x     = (const float*)d_in[0];
    const float* cosb  = (const float*)d_in[1];
    const float* sinb  = (const float*)d_in[2];
    const float* Wqkv  = (const float*)d_in[3];
    const float* Wproj = (const float*)d_in[4];
    float* out = (float*)d_out;

    float* qkv = nullptr;
    __nv_bfloat16 *atth, *attl;
    __half *ahi, *bhi, *blo;
    cudaGetSymbolAddress((void**)&qkv,  g_qkv);
    cudaGetSymbolAddress((void**)&atth, g_att_hi);
    cudaGetSymbolAddress((void**)&attl, g_att_lo);
    cudaGetSymbolAddress((void**)&ahi,  g_a_hi);
    cudaGetSymbolAddress((void**)&bhi,  g_b_hi);
    cudaGetSymbolAddress((void**)&blo,  g_b_lo);

    cudaFuncSetAttribute(hmma_gemm, cudaFuncAttributeMaxDynamicSharedMemorySize,
                         GEMM_SMEM);
    cudaFuncSetAttribute(attn_hmma, cudaFuncAttributeMaxDynamicSharedMemorySize,
                         ATT_SMEM);

    // ---- GEMM 1: qkv = x @ Wqkv^T ----
    {
        int n8a = M_ * C_ / 8, n8b = NQKV_ * C_ / 8;
        convert_f16_kernel<<<(n8a + 255) / 256, 256>>>(x, ahi, n8a);
        split_f16_kernel<<<(n8b + 255) / 256, 256>>>(Wqkv, bhi, blo, n8b);
        hmma_gemm<<<dim3(M_ / BM, NQKV_ / BN), 256, GEMM_SMEM>>>(
            ahi, bhi, blo, qkv, NQKV_, C_);
    }

    // ---- RoPE + bf16 conversion ----
    {
        int total = M_ * NG_ * 6 * 16;
        rope_split_kernel<<<(total + 255) / 256, 256>>>(qkv, cosb, sinb, atth, attl);
    }

    // ---- HMMA attention -> y (fp16 hi into GEMM2 A buffer) ----
    attn_hmma<<<dim3(T_ / 128, B_ * NH_), 256, ATT_SMEM>>>(atth, attl, ahi);

    // ---- GEMM 2: out = y @ Wproj^T ----
    {
        int n8b = C_ * C_ / 8;
        split_f16_kernel<<<(n8b + 255) / 256, 256>>>(Wproj, bhi, blo, n8b);
        hmma_gemm<<<dim3(M_ / BM, C_ / BN), 256, GEMM_SMEM>>>(
            ahi, bhi, blo, out, C_, C_);
    }
}

// round 10
// speedup vs baseline: 4.7332x; 1.0894x over previous
#include <cuda_runtime.h>
#include <cuda_bf16.h>
#include <cuda_fp16.h>
#include <math.h>
#include <stdint.h>

// Problem constants
#define B_    2
#define T_    2048
#define C_    4096
#define NH_   32
#define NG_   8
#define HS_   128
#define M_    (B_ * T_)                 // 4096 rows
#define NQKV_ ((NH_ + 2 * NG_) * HS_)   // 6144

// Scratch (no cudaMalloc allowed)
__device__ float g_qkv[(size_t)M_ * NQKV_];               // 100.7 MB fp32 qkv
__device__ __half g_att[(size_t)M_ * NQKV_];              // 50 MB roped q,k + v (fp16)
__device__ __half g_a_hi[(size_t)M_ * C_];                // 32 MB (x hi / y hi)
__device__ __half g_b_hi[(size_t)NQKV_ * C_];             // 48 MB (W hi)
__device__ __half g_b_lo[(size_t)NQKV_ * C_];             // 48 MB (W lo)

// ===========================================================================
// PTX helpers
// ===========================================================================
__device__ __forceinline__ uint32_t smem_to_u32(const void* p) {
    uint32_t a;
    asm("{ .reg .u64 t; cvta.to.shared.u64 t, %1; cvt.u32.u64 %0, t; }"
        : "=r"(a) : "l"(p));
    return a;
}
__device__ __forceinline__ void cp_async16(uint32_t dst, const void* src) {
    asm volatile("cp.async.cg.shared.global [%0], [%1], 16;" :: "r"(dst), "l"(src));
}
__device__ __forceinline__ void cp_commit() {
    asm volatile("cp.async.commit_group;");
}
template <int N> __device__ __forceinline__ void cp_wait() {
    asm volatile("cp.async.wait_group %0;" :: "n"(N));
}
__device__ __forceinline__ void ldsm4(uint32_t* r, uint32_t addr) {
    asm volatile("ldmatrix.sync.aligned.m8n8.x4.shared.b16 {%0,%1,%2,%3}, [%4];"
        : "=r"(r[0]), "=r"(r[1]), "=r"(r[2]), "=r"(r[3]) : "r"(addr));
}
__device__ __forceinline__ void ldsm4t(uint32_t* r, uint32_t addr) {
    asm volatile("ldmatrix.sync.aligned.m8n8.x4.trans.shared.b16 {%0,%1,%2,%3}, [%4];"
        : "=r"(r[0]), "=r"(r[1]), "=r"(r[2]), "=r"(r[3]) : "r"(addr));
}
__device__ __forceinline__ void mma_f16(float* d, const uint32_t* a,
                                        uint32_t b0, uint32_t b1) {
    asm volatile(
        "mma.sync.aligned.m16n8k16.row.col.f32.f16.f16.f32 "
        "{%0,%1,%2,%3}, {%4,%5,%6,%7}, {%8,%9}, {%0,%1,%2,%3};"
        : "+f"(d[0]), "+f"(d[1]), "+f"(d[2]), "+f"(d[3])
        : "r"(a[0]), "r"(a[1]), "r"(a[2]), "r"(a[3]), "r"(b0), "r"(b1));
}

// ===========================================================================
// fp16 2-pass HMMA GEMM: C = Ahi@Bhi^T + Ahi@Blo^T  (validated in R8)
// 128x128x32 tiles, 256 threads (8 warps 4x2), 2-stage double buffer,
// 3 matrices/stage (61.5KB) -> 2 CTAs/SM.
// ===========================================================================
#define BM 128
#define BN 128
#define BK 32
#define PADK 40
#define MAT_ELEMS (128 * PADK)            // 5120 halves
#define STAGE_ELEMS (3 * MAT_ELEMS)       // 15360 halves
#define NSTAGE 2
#define GEMM_SMEM (NSTAGE * STAGE_ELEMS * 2)   // 61440 B

__global__ __launch_bounds__(256, 2) void hmma_gemm(
    const __half* __restrict__ Ahi,
    const __half* __restrict__ Bhi, const __half* __restrict__ Blo,
    float* __restrict__ C, int Ntot, int K)
{
    extern __shared__ __half smb[];
    const int tid  = threadIdx.x;
    const int wid  = tid >> 5;
    const int lane = tid & 31;
    const int wm   = wid & 3;
    const int wn   = wid >> 2;
    const int m0   = blockIdx.x * BM;
    const int n0   = blockIdx.y * BN;
    const uint32_t sbase = smem_to_u32(smb);

    float acc[2][8][4];
#pragma unroll
    for (int i = 0; i < 2; i++)
#pragma unroll
        for (int j = 0; j < 8; j++)
#pragma unroll
            for (int v = 0; v < 4; v++) acc[i][j][v] = 0.f;

    auto issue_stage = [&](int s, int k0) {
        uint32_t dstb = sbase + s * (STAGE_ELEMS * 2);
#pragma unroll
        for (int i = 0; i < 6; i++) {
            int idx = i * 256 + tid;
            int mat = idx >> 9;              // 0=Ahi 1=Bhi 2=Blo
            int rem = idx & 511;
            int row = rem >> 2;
            int ch  = rem & 3;
            int grow = (mat == 0) ? (m0 + row) : (n0 + row);
            const __half* base = (mat == 0) ? Ahi : (mat == 1) ? Bhi : Blo;
            const __half* src = base + (size_t)grow * K + k0 + ch * 8;
            uint32_t d = dstb + (uint32_t)(mat * MAT_ELEMS + row * PADK + ch * 8) * 2;
            cp_async16(d, src);
        }
    };

    const uint32_t offA = (uint32_t)((wm * 32 + (lane & 15)) * PADK + (lane >> 4) * 8) * 2;
    const uint32_t offB = (uint32_t)(MAT_ELEMS +
        (wn * 64 + (lane & 7) + ((lane >> 4) << 3)) * PADK + ((lane >> 3) & 1) * 8) * 2;

    issue_stage(0, 0);    cp_commit();
    issue_stage(1, BK);   cp_commit();

    const int nk = K / BK;
    for (int it = 0; it < nk; it++) {
        if (it + 1 < nk) cp_wait<1>();
        else             cp_wait<0>();
        __syncthreads();

        const uint32_t stb = sbase + (it & 1) * (STAGE_ELEMS * 2);
#pragma unroll
        for (int kk = 0; kk < 2; kk++) {
            uint32_t ah[2][4], bh[4][4], bl[4][4];
#pragma unroll
            for (int mt = 0; mt < 2; mt++) {
                uint32_t a = stb + offA + (uint32_t)(mt * 16 * PADK + kk * 16) * 2;
                ldsm4(ah[mt], a);
            }
#pragma unroll
            for (int nt = 0; nt < 4; nt++) {
                uint32_t a = stb + offB + (uint32_t)(nt * 16 * PADK + kk * 16) * 2;
                ldsm4(bh[nt], a);
                ldsm4(bl[nt], a + MAT_ELEMS * 2);
            }
#pragma unroll
            for (int mt = 0; mt < 2; mt++)
#pragma unroll
                for (int n8 = 0; n8 < 8; n8++)
                    mma_f16(acc[mt][n8], ah[mt],
                            bh[n8 >> 1][(n8 & 1) * 2], bh[n8 >> 1][(n8 & 1) * 2 + 1]);
#pragma unroll
            for (int mt = 0; mt < 2; mt++)
#pragma unroll
                for (int n8 = 0; n8 < 8; n8++)
                    mma_f16(acc[mt][n8], ah[mt],
                            bl[n8 >> 1][(n8 & 1) * 2], bl[n8 >> 1][(n8 & 1) * 2 + 1]);
        }
        __syncthreads();
        if (it + 2 < nk) {
            issue_stage(it & 1, (it + 2) * BK);
            cp_commit();
        }
    }

#pragma unroll
    for (int mt = 0; mt < 2; mt++) {
        int r0 = m0 + wm * 32 + mt * 16 + (lane >> 2);
#pragma unroll
        for (int n8 = 0; n8 < 8; n8++) {
            int col = n0 + wn * 64 + n8 * 8 + (lane & 3) * 2;
            *(float2*)(C + (size_t)r0 * Ntot + col) =
                make_float2(acc[mt][n8][0], acc[mt][n8][1]);
            *(float2*)(C + (size_t)(r0 + 8) * Ntot + col) =
                make_float2(acc[mt][n8][2], acc[mt][n8][3]);
        }
    }
}

// ===========================================================================
// fp32 -> fp16 hi/lo split (weights)
// ===========================================================================
__global__ void split_f16_kernel(const float* __restrict__ in,
                                 __half* __restrict__ hi,
                                 __half* __restrict__ lo, int n8)
{
    int i = blockIdx.x * blockDim.x + threadIdx.x;
    if (i >= n8) return;
    float4 va = *(const float4*)(in + (size_t)i * 8);
    float4 vb = *(const float4*)(in + (size_t)i * 8 + 4);
    float f[8] = {va.x, va.y, va.z, va.w, vb.x, vb.y, vb.z, vb.w};
    uint32_t hw[4], lw[4];
#pragma unroll
    for (int j = 0; j < 4; j++) {
        __half h0 = __float2half_rn(f[2 * j]);
        __half h1 = __float2half_rn(f[2 * j + 1]);
        __half2 hp = __halves2half2(h0, h1);
        __half2 lp = __halves2half2(
            __float2half_rn(f[2 * j]     - __half2float(h0)),
            __float2half_rn(f[2 * j + 1] - __half2float(h1)));
        hw[j] = *(uint32_t*)&hp;
        lw[j] = *(uint32_t*)&lp;
    }
    *(uint4*)(hi + (size_t)i * 8) = make_uint4(hw[0], hw[1], hw[2], hw[3]);
    *(uint4*)(lo + (size_t)i * 8) = make_uint4(lw[0], lw[1], lw[2], lw[3]);
}

// fp32 -> fp16 hi only (activations)
__global__ void convert_f16_kernel(const float* __restrict__ in,
                                   __half* __restrict__ hi, int n8)
{
    int i = blockIdx.x * blockDim.x + threadIdx.x;
    if (i >= n8) return;
    float4 va = *(const float4*)(in + (size_t)i * 8);
    float4 vb = *(const float4*)(in + (size_t)i * 8 + 4);
    __half2 h0 = __floats2half2_rn(va.x, va.y);
    __half2 h1 = __floats2half2_rn(va.z, va.w);
    __half2 h2 = __floats2half2_rn(vb.x, vb.y);
    __half2 h3 = __floats2half2_rn(vb.z, vb.w);
    *(uint4*)(hi + (size_t)i * 8) = make_uint4(
        *(uint32_t*)&h0, *(uint32_t*)&h1, *(uint32_t*)&h2, *(uint32_t*)&h3);
}

// ===========================================================================
// RoPE + fp16 conversion: q,k slots roped, v converted. All fp16 hi-only.
// ===========================================================================
__global__ void rope_f16_kernel(const float* __restrict__ qkv,
                                const float* __restrict__ cs,
                                const float* __restrict__ sn,
                                __half* __restrict__ ah)
{
    int idx = blockIdx.x * blockDim.x + threadIdx.x;
    const int total = M_ * NG_ * 6 * 16;
    if (idx >= total) return;

    int d4 = (idx & 15) * 4;
    int r = idx >> 4;
    int slot = r % 6; r /= 6;
    int g    = r % NG_; r /= NG_;
    int t = r & (T_ - 1);

    size_t off = (size_t)r * NQKV_ + g * 768 + slot * 128;
    const float* p = qkv + off;
    float4 x1 = *(const float4*)(p + d4);
    float4 x2 = *(const float4*)(p + d4 + 64);

    float o1[4], o2[4];
    if (slot < 5) {
        float4 c1 = *(const float4*)(cs + t * HS_ + d4);
        float4 s1 = *(const float4*)(sn + t * HS_ + d4);
        float4 c2 = *(const float4*)(cs + t * HS_ + d4 + 64);
        float4 s2 = *(const float4*)(sn + t * HS_ + d4 + 64);
        o1[0] = x1.x * c1.x - x2.x * s1.x;  o2[0] = x2.x * c2.x + x1.x * s2.x;
        o1[1] = x1.y * c1.y - x2.y * s1.y;  o2[1] = x2.y * c2.y + x1.y * s2.y;
        o1[2] = x1.z * c1.z - x2.z * s1.z;  o2[2] = x2.z * c2.z + x1.z * s2.z;
        o1[3] = x1.w * c1.w - x2.w * s1.w;  o2[3] = x2.w * c2.w + x1.w * s2.w;
    } else {
        o1[0] = x1.x; o1[1] = x1.y; o1[2] = x1.z; o1[3] = x1.w;
        o2[0] = x2.x; o2[1] = x2.y; o2[2] = x2.z; o2[3] = x2.w;
    }
    __half2 w10 = __floats2half2_rn(o1[0], o1[1]);
    __half2 w11 = __floats2half2_rn(o1[2], o1[3]);
    __half2 w20 = __floats2half2_rn(o2[0], o2[1]);
    __half2 w21 = __floats2half2_rn(o2[2], o2[3]);
    *(uint2*)(ah + off + d4)      = make_uint2(*(uint32_t*)&w10, *(uint32_t*)&w11);
    *(uint2*)(ah + off + d4 + 64) = make_uint2(*(uint32_t*)&w20, *(uint32_t*)&w21);
}

// ===========================================================================
// fp16 HMMA causal flash attention. 256 thr (8 warps), 128 q-rows/block,
// 64-key tiles double-buffered, 104KB smem -> 2 CTAs/SM.
// QK fp16 1 pass; PV fp16 1 pass. Output y fp16.
// ===========================================================================
#define AT_PAD 136
#define AT_TILE_E (64 * AT_PAD)
#define AT_Q_E (128 * AT_PAD)
#define ATT_SMEM ((AT_Q_E + 4 * AT_TILE_E) * 2)   // 104448 B

__global__ __launch_bounds__(256, 2) void attn_hmma(
    const __half* __restrict__ ah, __half* __restrict__ yhi)
{
    extern __shared__ __half smq[];
    const int tid  = threadIdx.x;
    const int wid  = tid >> 5;
    const int lane = tid & 31;
    const int qtb = gridDim.x - 1 - blockIdx.x;   // big blocks first
    const int bh = blockIdx.y;
    const int b = bh >> 5, h = bh & 31, g = h >> 2, qi = h & 3;
    const size_t rowbase = (size_t)b * T_ * NQKV_ + g * 768;
    const __half* qb = ah + rowbase + qi * 128;
    const __half* kb = ah + rowbase + 512;
    const __half* vh = ah + rowbase + 640;
    const int q0 = qtb * 128;
    const int ntiles = 2 * qtb + 2;

    const uint32_t sb = smem_to_u32(smq);
    const uint32_t Qs = sb;
    uint32_t St[2];
    St[0] = sb + AT_Q_E * 2;
    St[1] = St[0] + 2 * AT_TILE_E * 2;

    // Q tile: 128 rows x 16 chunks
#pragma unroll
    for (int i = 0; i < 8; i++) {
        int idx = i * 256 + tid;
        int row = idx >> 4, ch = idx & 15;
        cp_async16(Qs + (uint32_t)(row * AT_PAD + ch * 8) * 2,
                   qb + (size_t)(q0 + row) * NQKV_ + ch * 8);
    }

    auto issue_kv = [&](int st, int k0) {
        uint32_t base = St[st];
#pragma unroll
        for (int i = 0; i < 8; i++) {
            int idx = i * 256 + tid;
            int arr = idx >> 10;              // 0=K 1=V
            int rem = idx & 1023;
            int row = rem >> 4, ch = rem & 15;
            const __half* src = (arr == 0 ? kb : vh) + (size_t)(k0 + row) * NQKV_ + ch * 8;
            cp_async16(base + (uint32_t)(arr * AT_TILE_E + row * AT_PAD + ch * 8) * 2, src);
        }
    };
    issue_kv(0, 0);
    cp_commit();

    float m_[2] = {-1e30f, -1e30f}, l_[2] = {0.f, 0.f};
    float O[16][4];
#pragma unroll
    for (int n = 0; n < 16; n++)
#pragma unroll
        for (int v = 0; v < 4; v++) O[n][v] = 0.f;

    const float sc = 0.08838834764831845f;
    const int r1 = lane >> 2;
    const int qw = q0 + wid * 16;

    for (int kt = 0; kt < ntiles; kt++) {
        const int st = kt & 1;
        const int k0 = kt * 64;
        if (kt + 1 < ntiles) {
            issue_kv(st ^ 1, (kt + 1) * 64);
            cp_commit();
            cp_wait<1>();
        } else {
            cp_wait<0>();
        }
        __syncthreads();

        const uint32_t Ks  = St[st];
        const uint32_t Vhs = St[st] + AT_TILE_E * 2;

        // ---- S = Q K^T ----
        float s[8][4];
#pragma unroll
        for (int j = 0; j < 8; j++)
#pragma unroll
            for (int v = 0; v < 4; v++) s[j][v] = 0.f;

#pragma unroll
        for (int t = 0; t < 8; t++) {
            uint32_t a[4];
            ldsm4(a, Qs + (uint32_t)((wid * 16 + (lane & 15)) * AT_PAD +
                                     t * 16 + (lane >> 4) * 8) * 2);
#pragma unroll
            for (int u = 0; u < 4; u++) {
                uint32_t bb[4];
                ldsm4(bb, Ks + (uint32_t)((u * 16 + ((lane >> 4) << 3) + (lane & 7)) * AT_PAD +
                                          t * 16 + ((lane >> 3) & 1) * 8) * 2);
                mma_f16(s[2 * u],     a, bb[0], bb[1]);
                mma_f16(s[2 * u + 1], a, bb[2], bb[3]);
            }
        }

#pragma unroll
        for (int j = 0; j < 8; j++)
#pragma unroll
            for (int v = 0; v < 4; v++) s[j][v] *= sc;

        if (k0 + 63 > qw) {
#pragma unroll
            for (int j = 0; j < 8; j++)
#pragma unroll
                for (int v = 0; v < 4; v++) {
                    int key = k0 + j * 8 + (lane & 3) * 2 + (v & 1);
                    int qr  = qw + r1 + ((v >> 1) << 3);
                    if (key > qr) s[j][v] = -1e30f;
                }
        }

        // ---- online softmax ----
#pragma unroll
        for (int rr = 0; rr < 2; rr++) {
            float mx = -1e30f;
#pragma unroll
            for (int j = 0; j < 8; j++) {
                mx = fmaxf(mx, s[j][rr * 2]);
                mx = fmaxf(mx, s[j][rr * 2 + 1]);
            }
            mx = fmaxf(mx, __shfl_xor_sync(0xffffffffu, mx, 1));
            mx = fmaxf(mx, __shfl_xor_sync(0xffffffffu, mx, 2));
            float mnew = fmaxf(m_[rr], mx);
            float corr = __expf(m_[rr] - mnew);
            float sum = 0.f;
#pragma unroll
            for (int j = 0; j < 8; j++) {
                float p0 = __expf(s[j][rr * 2]     - mnew);
                float p1 = __expf(s[j][rr * 2 + 1] - mnew);
                s[j][rr * 2]     = p0;
                s[j][rr * 2 + 1] = p1;
                sum += p0 + p1;
            }
            sum += __shfl_xor_sync(0xffffffffu, sum, 1);
            sum += __shfl_xor_sync(0xffffffffu, sum, 2);
            l_[rr] = l_[rr] * corr + sum;
            m_[rr] = mnew;
#pragma unroll
            for (int n = 0; n < 16; n++) {
                O[n][rr * 2]     *= corr;
                O[n][rr * 2 + 1] *= corr;
            }
        }

        // ---- O += P V (fp16 single pass) ----
#pragma unroll
        for (int t = 0; t < 4; t++) {
            uint32_t phi[4];
#pragma unroll
            for (int v = 0; v < 2; v++) {
                __half2 hp0 = __floats2half2_rn(s[2 * t][v * 2], s[2 * t][v * 2 + 1]);
                __half2 hp1 = __floats2half2_rn(s[2 * t + 1][v * 2], s[2 * t + 1][v * 2 + 1]);
                phi[v]     = *(uint32_t*)&hp0;
                phi[v + 2] = *(uint32_t*)&hp1;
            }
#pragma unroll
            for (int dg = 0; dg < 8; dg++) {
                uint32_t roff = (uint32_t)((t * 16 + ((lane >> 3) & 1) * 8 + (lane & 7)) * AT_PAD +
                                           dg * 16 + (lane >> 4) * 8) * 2;
                uint32_t bhv[4];
                ldsm4t(bhv, Vhs + roff);
                mma_f16(O[2 * dg],     phi, bhv[0], bhv[1]);
                mma_f16(O[2 * dg + 1], phi, bhv[2], bhv[3]);
            }
        }
        __syncthreads();
    }

    // Epilogue: normalize, write y fp16
#pragma unroll
    for (int rr = 0; rr < 2; rr++) {
        float inv = 1.f / l_[rr];
        int row = qw + r1 + rr * 8;
        size_t rb = (size_t)(b * T_ + row) * C_ + h * 128;
#pragma unroll
        for (int n = 0; n < 16; n++) {
            int col = n * 8 + (lane & 3) * 2;
            __half2 hp = __floats2half2_rn(O[n][rr * 2] * inv,
                                           O[n][rr * 2 + 1] * inv);
            *(uint32_t*)(yhi + rb + col) = *(uint32_t*)&hp;
        }
    }
}

// ===========================================================================
// Launch
// ===========================================================================
extern "C" void kernel_launch(void* const* d_in, const int* in_sizes, int n_in,
                              void* d_out, int out_size)
{
    const float* x     = (const float*)d_in[0];
    const float* cosb  = (const float*)d_in[1];
    const float* sinb  = (const float*)d_in[2];
    const float* Wqkv  = (const float*)d_in[3];
    const float* Wproj = (const float*)d_in[4];
    float* out = (float*)d_out;

    float* qkv = nullptr;
    __half *atth, *ahi, *bhi, *blo;
    cudaGetSymbolAddress((void**)&qkv,  g_qkv);
    cudaGetSymbolAddress((void**)&atth, g_att);
    cudaGetSymbolAddress((void**)&ahi,  g_a_hi);
    cudaGetSymbolAddress((void**)&bhi,  g_b_hi);
    cudaGetSymbolAddress((void**)&blo,  g_b_lo);

    cudaFuncSetAttribute(hmma_gemm, cudaFuncAttributeMaxDynamicSharedMemorySize,
                         GEMM_SMEM);
    cudaFuncSetAttribute(attn_hmma, cudaFuncAttributeMaxDynamicSharedMemorySize,
                         ATT_SMEM);

    // ---- GEMM 1: qkv = x @ Wqkv^T ----
    {
        int n8a = M_ * C_ / 8, n8b = NQKV_ * C_ / 8;
        convert_f16_kernel<<<(n8a + 255) / 256, 256>>>(x, ahi, n8a);
        split_f16_kernel<<<(n8b + 255) / 256, 256>>>(Wqkv, bhi, blo, n8b);
        hmma_gemm<<<dim3(M_ / BM, NQKV_ / BN), 256, GEMM_SMEM>>>(
            ahi, bhi, blo, qkv, NQKV_, C_);
    }

    // ---- RoPE + fp16 conversion ----
    {
        int total = M_ * NG_ * 6 * 16;
        rope_f16_kernel<<<(total + 255) / 256, 256>>>(qkv, cosb, sinb, atth);
    }

    // ---- fp16 attention -> y (fp16 into GEMM2 A buffer) ----
    attn_hmma<<<dim3(T_ / 128, B_ * NH_), 256, ATT_SMEM>>>(atth, ahi);

    // ---- GEMM 2: out = y @ Wproj^T ----
    {
        int n8b = C_ * C_ / 8;
        split_f16_kernel<<<(n8b + 255) / 256, 256>>>(Wproj, bhi, blo, n8b);
        hmma_gemm<<<dim3(M_ / BM, C_ / BN), 256, GEMM_SMEM>>>(
            ahi, bhi, blo, out, C_, C_);
    }
}

// round 11
// speedup vs baseline: 8.3101x; 1.7557x over previous
#include <cuda_runtime.h>
#include <cuda_bf16.h>
#include <cuda_fp16.h>
#include <math.h>
#include <stdint.h>

// Problem constants
#define B_    2
#define T_    2048
#define C_    4096
#define NH_   32
#define NG_   8
#define HS_   128
#define M_    (B_ * T_)                 // 4096 rows
#define NQKV_ ((NH_ + 2 * NG_) * HS_)   // 6144

// Scratch (no cudaMalloc allowed)
__device__ float g_qkv[(size_t)M_ * NQKV_];               // 100.7 MB fp32 qkv
__device__ __half g_att[(size_t)M_ * NQKV_];              // 50 MB roped q,k + v (fp16)
__device__ __half g_a_hi[(size_t)M_ * C_];                // 32 MB (x hi / y hi)
__device__ __half g_b_hi[(size_t)NQKV_ * C_];             // 48 MB (W hi)

// ===========================================================================
// PTX helpers
// ===========================================================================
__device__ __forceinline__ uint32_t smem_to_u32(const void* p) {
    uint32_t a;
    asm("{ .reg .u64 t; cvta.to.shared.u64 t, %1; cvt.u32.u64 %0, t; }"
        : "=r"(a) : "l"(p));
    return a;
}
__device__ __forceinline__ void cp_async16(uint32_t dst, const void* src) {
    asm volatile("cp.async.cg.shared.global [%0], [%1], 16;" :: "r"(dst), "l"(src));
}
__device__ __forceinline__ void cp_commit() {
    asm volatile("cp.async.commit_group;");
}
template <int N> __device__ __forceinline__ void cp_wait() {
    asm volatile("cp.async.wait_group %0;" :: "n"(N));
}
__device__ __forceinline__ void ldsm4(uint32_t* r, uint32_t addr) {
    asm volatile("ldmatrix.sync.aligned.m8n8.x4.shared.b16 {%0,%1,%2,%3}, [%4];"
        : "=r"(r[0]), "=r"(r[1]), "=r"(r[2]), "=r"(r[3]) : "r"(addr));
}
__device__ __forceinline__ void ldsm4t(uint32_t* r, uint32_t addr) {
    asm volatile("ldmatrix.sync.aligned.m8n8.x4.trans.shared.b16 {%0,%1,%2,%3}, [%4];"
        : "=r"(r[0]), "=r"(r[1]), "=r"(r[2]), "=r"(r[3]) : "r"(addr));
}
__device__ __forceinline__ void mma_f16(float* d, const uint32_t* a,
                                        uint32_t b0, uint32_t b1) {
    asm volatile(
        "mma.sync.aligned.m16n8k16.row.col.f32.f16.f16.f32 "
        "{%0,%1,%2,%3}, {%4,%5,%6,%7}, {%8,%9}, {%0,%1,%2,%3};"
        : "+f"(d[0]), "+f"(d[1]), "+f"(d[2]), "+f"(d[3])
        : "r"(a[0]), "r"(a[1]), "r"(a[2]), "r"(a[3]), "r"(b0), "r"(b1));
}

// ===========================================================================
// fp16 single-pass HMMA GEMM: C = Ahi @ Bhi^T
// 128x128x32 tiles, 256 threads (8 warps 4x2), 2-stage double buffer,
// 2 matrices/stage (40KB total) -> 2 CTAs/SM.
// ===========================================================================
#define BM 128
#define BN 128
#define BK 32
#define PADK 40
#define MAT_ELEMS (128 * PADK)            // 5120 halves
#define STAGE_ELEMS (2 * MAT_ELEMS)       // 10240 halves
#define NSTAGE 2
#define GEMM_SMEM (NSTAGE * STAGE_ELEMS * 2)   // 40960 B

__global__ __launch_bounds__(256, 2) void hmma_gemm(
    const __half* __restrict__ Ahi, const __half* __restrict__ Bhi,
    float* __restrict__ C, int Ntot, int K)
{
    extern __shared__ __half smb[];
    const int tid  = threadIdx.x;
    const int wid  = tid >> 5;
    const int lane = tid & 31;
    const int wm   = wid & 3;
    const int wn   = wid >> 2;
    const int m0   = blockIdx.x * BM;
    const int n0   = blockIdx.y * BN;
    const uint32_t sbase = smem_to_u32(smb);

    float acc[2][8][4];
#pragma unroll
    for (int i = 0; i < 2; i++)
#pragma unroll
        for (int j = 0; j < 8; j++)
#pragma unroll
            for (int v = 0; v < 4; v++) acc[i][j][v] = 0.f;

    auto issue_stage = [&](int s, int k0) {
        uint32_t dstb = sbase + s * (STAGE_ELEMS * 2);
#pragma unroll
        for (int i = 0; i < 4; i++) {
            int idx = i * 256 + tid;
            int mat = idx >> 9;              // 0=Ahi 1=Bhi
            int rem = idx & 511;
            int row = rem >> 2;
            int ch  = rem & 3;
            int grow = (mat == 0) ? (m0 + row) : (n0 + row);
            const __half* base = (mat == 0) ? Ahi : Bhi;
            const __half* src = base + (size_t)grow * K + k0 + ch * 8;
            uint32_t d = dstb + (uint32_t)(mat * MAT_ELEMS + row * PADK + ch * 8) * 2;
            cp_async16(d, src);
        }
    };

    const uint32_t offA = (uint32_t)((wm * 32 + (lane & 15)) * PADK + (lane >> 4) * 8) * 2;
    const uint32_t offB = (uint32_t)(MAT_ELEMS +
        (wn * 64 + (lane & 7) + ((lane >> 4) << 3)) * PADK + ((lane >> 3) & 1) * 8) * 2;

    issue_stage(0, 0);    cp_commit();
    issue_stage(1, BK);   cp_commit();

    const int nk = K / BK;
    for (int it = 0; it < nk; it++) {
        if (it + 1 < nk) cp_wait<1>();
        else             cp_wait<0>();
        __syncthreads();

        const uint32_t stb = sbase + (it & 1) * (STAGE_ELEMS * 2);
#pragma unroll
        for (int kk = 0; kk < 2; kk++) {
            uint32_t ah[2][4], bh[4][4];
#pragma unroll
            for (int mt = 0; mt < 2; mt++) {
                uint32_t a = stb + offA + (uint32_t)(mt * 16 * PADK + kk * 16) * 2;
                ldsm4(ah[mt], a);
            }
#pragma unroll
            for (int nt = 0; nt < 4; nt++) {
                uint32_t a = stb + offB + (uint32_t)(nt * 16 * PADK + kk * 16) * 2;
                ldsm4(bh[nt], a);
            }
#pragma unroll
            for (int mt = 0; mt < 2; mt++)
#pragma unroll
                for (int n8 = 0; n8 < 8; n8++)
                    mma_f16(acc[mt][n8], ah[mt],
                            bh[n8 >> 1][(n8 & 1) * 2], bh[n8 >> 1][(n8 & 1) * 2 + 1]);
        }
        __syncthreads();
        if (it + 2 < nk) {
            issue_stage(it & 1, (it + 2) * BK);
            cp_commit();
        }
    }

#pragma unroll
    for (int mt = 0; mt < 2; mt++) {
        int r0 = m0 + wm * 32 + mt * 16 + (lane >> 2);
#pragma unroll
        for (int n8 = 0; n8 < 8; n8++) {
            int col = n0 + wn * 64 + n8 * 8 + (lane & 3) * 2;
            *(float2*)(C + (size_t)r0 * Ntot + col) =
                make_float2(acc[mt][n8][0], acc[mt][n8][1]);
            *(float2*)(C + (size_t)(r0 + 8) * Ntot + col) =
                make_float2(acc[mt][n8][2], acc[mt][n8][3]);
        }
    }
}

// ===========================================================================
// fp32 -> fp16 (hi only); 8 elements per thread
// ===========================================================================
__global__ void convert_f16_kernel(const float* __restrict__ in,
                                   __half* __restrict__ hi, int n8)
{
    int i = blockIdx.x * blockDim.x + threadIdx.x;
    if (i >= n8) return;
    float4 va = *(const float4*)(in + (size_t)i * 8);
    float4 vb = *(const float4*)(in + (size_t)i * 8 + 4);
    __half2 h0 = __floats2half2_rn(va.x, va.y);
    __half2 h1 = __floats2half2_rn(va.z, va.w);
    __half2 h2 = __floats2half2_rn(vb.x, vb.y);
    __half2 h3 = __floats2half2_rn(vb.z, vb.w);
    *(uint4*)(hi + (size_t)i * 8) = make_uint4(
        *(uint32_t*)&h0, *(uint32_t*)&h1, *(uint32_t*)&h2, *(uint32_t*)&h3);
}

// ===========================================================================
// RoPE + fp16 conversion: q,k slots roped, v converted. All fp16 hi-only.
// ===========================================================================
__global__ void rope_f16_kernel(const float* __restrict__ qkv,
                                const float* __restrict__ cs,
                                const float* __restrict__ sn,
                                __half* __restrict__ ah)
{
    int idx = blockIdx.x * blockDim.x + threadIdx.x;
    const int total = M_ * NG_ * 6 * 16;
    if (idx >= total) return;

    int d4 = (idx & 15) * 4;
    int r = idx >> 4;
    int slot = r % 6; r /= 6;
    int g    = r % NG_; r /= NG_;
    int t = r & (T_ - 1);

    size_t off = (size_t)r * NQKV_ + g * 768 + slot * 128;
    const float* p = qkv + off;
    float4 x1 = *(const float4*)(p + d4);
    float4 x2 = *(const float4*)(p + d4 + 64);

    float o1[4], o2[4];
    if (slot < 5) {
        float4 c1 = *(const float4*)(cs + t * HS_ + d4);
        float4 s1 = *(const float4*)(sn + t * HS_ + d4);
        float4 c2 = *(const float4*)(cs + t * HS_ + d4 + 64);
        float4 s2 = *(const float4*)(sn + t * HS_ + d4 + 64);
        o1[0] = x1.x * c1.x - x2.x * s1.x;  o2[0] = x2.x * c2.x + x1.x * s2.x;
        o1[1] = x1.y * c1.y - x2.y * s1.y;  o2[1] = x2.y * c2.y + x1.y * s2.y;
        o1[2] = x1.z * c1.z - x2.z * s1.z;  o2[2] = x2.z * c2.z + x1.z * s2.z;
        o1[3] = x1.w * c1.w - x2.w * s1.w;  o2[3] = x2.w * c2.w + x1.w * s2.w;
    } else {
        o1[0] = x1.x; o1[1] = x1.y; o1[2] = x1.z; o1[3] = x1.w;
        o2[0] = x2.x; o2[1] = x2.y; o2[2] = x2.z; o2[3] = x2.w;
    }
    __half2 w10 = __floats2half2_rn(o1[0], o1[1]);
    __half2 w11 = __floats2half2_rn(o1[2], o1[3]);
    __half2 w20 = __floats2half2_rn(o2[0], o2[1]);
    __half2 w21 = __floats2half2_rn(o2[2], o2[3]);
    *(uint2*)(ah + off + d4)      = make_uint2(*(uint32_t*)&w10, *(uint32_t*)&w11);
    *(uint2*)(ah + off + d4 + 64) = make_uint2(*(uint32_t*)&w20, *(uint32_t*)&w21);
}

// ===========================================================================
// fp16 HMMA causal flash attention (validated in R10).
// 256 thr (8 warps), 128 q-rows/block, 64-key tiles double-buffered,
// 104KB smem -> 2 CTAs/SM. QK fp16 1 pass; PV fp16 1 pass. Output y fp16.
// ===========================================================================
#define AT_PAD 136
#define AT_TILE_E (64 * AT_PAD)
#define AT_Q_E (128 * AT_PAD)
#define ATT_SMEM ((AT_Q_E + 4 * AT_TILE_E) * 2)   // 104448 B

__global__ __launch_bounds__(256, 2) void attn_hmma(
    const __half* __restrict__ ah, __half* __restrict__ yhi)
{
    extern __shared__ __half smq[];
    const int tid  = threadIdx.x;
    const int wid  = tid >> 5;
    const int lane = tid & 31;
    const int qtb = gridDim.x - 1 - blockIdx.x;   // big blocks first
    const int bh = blockIdx.y;
    const int b = bh >> 5, h = bh & 31, g = h >> 2, qi = h & 3;
    const size_t rowbase = (size_t)b * T_ * NQKV_ + g * 768;
    const __half* qb = ah + rowbase + qi * 128;
    const __half* kb = ah + rowbase + 512;
    const __half* vh = ah + rowbase + 640;
    const int q0 = qtb * 128;
    const int ntiles = 2 * qtb + 2;

    const uint32_t sb = smem_to_u32(smq);
    const uint32_t Qs = sb;
    uint32_t St[2];
    St[0] = sb + AT_Q_E * 2;
    St[1] = St[0] + 2 * AT_TILE_E * 2;

    // Q tile: 128 rows x 16 chunks
#pragma unroll
    for (int i = 0; i < 8; i++) {
        int idx = i * 256 + tid;
        int row = idx >> 4, ch = idx & 15;
        cp_async16(Qs + (uint32_t)(row * AT_PAD + ch * 8) * 2,
                   qb + (size_t)(q0 + row) * NQKV_ + ch * 8);
    }

    auto issue_kv = [&](int st, int k0) {
        uint32_t base = St[st];
#pragma unroll
        for (int i = 0; i < 8; i++) {
            int idx = i * 256 + tid;
            int arr = idx >> 10;              // 0=K 1=V
            int rem = idx & 1023;
            int row = rem >> 4, ch = rem & 15;
            const __half* src = (arr == 0 ? kb : vh) + (size_t)(k0 + row) * NQKV_ + ch * 8;
            cp_async16(base + (uint32_t)(arr * AT_TILE_E + row * AT_PAD + ch * 8) * 2, src);
        }
    };
    issue_kv(0, 0);
    cp_commit();

    float m_[2] = {-1e30f, -1e30f}, l_[2] = {0.f, 0.f};
    float O[16][4];
#pragma unroll
    for (int n = 0; n < 16; n++)
#pragma unroll
        for (int v = 0; v < 4; v++) O[n][v] = 0.f;

    const float sc = 0.08838834764831845f;
    const int r1 = lane >> 2;
    const int qw = q0 + wid * 16;

    for (int kt = 0; kt < ntiles; kt++) {
        const int st = kt & 1;
        const int k0 = kt * 64;
        if (kt + 1 < ntiles) {
            issue_kv(st ^ 1, (kt + 1) * 64);
            cp_commit();
            cp_wait<1>();
        } else {
            cp_wait<0>();
        }
        __syncthreads();

        const uint32_t Ks  = St[st];
        const uint32_t Vhs = St[st] + AT_TILE_E * 2;

        // ---- S = Q K^T ----
        float s[8][4];
#pragma unroll
        for (int j = 0; j < 8; j++)
#pragma unroll
            for (int v = 0; v < 4; v++) s[j][v] = 0.f;

#pragma unroll
        for (int t = 0; t < 8; t++) {
            uint32_t a[4];
            ldsm4(a, Qs + (uint32_t)((wid * 16 + (lane & 15)) * AT_PAD +
                                     t * 16 + (lane >> 4) * 8) * 2);
#pragma unroll
            for (int u = 0; u < 4; u++) {
                uint32_t bb[4];
                ldsm4(bb, Ks + (uint32_t)((u * 16 + ((lane >> 4) << 3) + (lane & 7)) * AT_PAD +
                                          t * 16 + ((lane >> 3) & 1) * 8) * 2);
                mma_f16(s[2 * u],     a, bb[0], bb[1]);
                mma_f16(s[2 * u + 1], a, bb[2], bb[3]);
            }
        }

#pragma unroll
        for (int j = 0; j < 8; j++)
#pragma unroll
            for (int v = 0; v < 4; v++) s[j][v] *= sc;

        if (k0 + 63 > qw) {
#pragma unroll
            for (int j = 0; j < 8; j++)
#pragma unroll
                for (int v = 0; v < 4; v++) {
                    int key = k0 + j * 8 + (lane & 3) * 2 + (v & 1);
                    int qr  = qw + r1 + ((v >> 1) << 3);
                    if (key > qr) s[j][v] = -1e30f;
                }
        }

        // ---- online softmax ----
#pragma unroll
        for (int rr = 0; rr < 2; rr++) {
            float mx = -1e30f;
#pragma unroll
            for (int j = 0; j < 8; j++) {
                mx = fmaxf(mx, s[j][rr * 2]);
                mx = fmaxf(mx, s[j][rr * 2 + 1]);
            }
            mx = fmaxf(mx, __shfl_xor_sync(0xffffffffu, mx, 1));
            mx = fmaxf(mx, __shfl_xor_sync(0xffffffffu, mx, 2));
            float mnew = fmaxf(m_[rr], mx);
            float corr = __expf(m_[rr] - mnew);
            float sum = 0.f;
#pragma unroll
            for (int j = 0; j < 8; j++) {
                float p0 = __expf(s[j][rr * 2]     - mnew);
                float p1 = __expf(s[j][rr * 2 + 1] - mnew);
                s[j][rr * 2]     = p0;
                s[j][rr * 2 + 1] = p1;
                sum += p0 + p1;
            }
            sum += __shfl_xor_sync(0xffffffffu, sum, 1);
            sum += __shfl_xor_sync(0xffffffffu, sum, 2);
            l_[rr] = l_[rr] * corr + sum;
            m_[rr] = mnew;
#pragma unroll
            for (int n = 0; n < 16; n++) {
                O[n][rr * 2]     *= corr;
                O[n][rr * 2 + 1] *= corr;
            }
        }

        // ---- O += P V (fp16 single pass) ----
#pragma unroll
        for (int t = 0; t < 4; t++) {
            uint32_t phi[4];
#pragma unroll
            for (int v = 0; v < 2; v++) {
                __half2 hp0 = __floats2half2_rn(s[2 * t][v * 2], s[2 * t][v * 2 + 1]);
                __half2 hp1 = __floats2half2_rn(s[2 * t + 1][v * 2], s[2 * t + 1][v * 2 + 1]);
                phi[v]     = *(uint32_t*)&hp0;
                phi[v + 2] = *(uint32_t*)&hp1;
            }
#pragma unroll
            for (int dg = 0; dg < 8; dg++) {
                uint32_t roff = (uint32_t)((t * 16 + ((lane >> 3) & 1) * 8 + (lane & 7)) * AT_PAD +
                                           dg * 16 + (lane >> 4) * 8) * 2;
                uint32_t bhv[4];
                ldsm4t(bhv, Vhs + roff);
                mma_f16(O[2 * dg],     phi, bhv[0], bhv[1]);
                mma_f16(O[2 * dg + 1], phi, bhv[2], bhv[3]);
            }
        }
        __syncthreads();
    }

    // Epilogue: normalize, write y fp16
#pragma unroll
    for (int rr = 0; rr < 2; rr++) {
        float inv = 1.f / l_[rr];
        int row = qw + r1 + rr * 8;
        size_t rb = (size_t)(b * T_ + row) * C_ + h * 128;
#pragma unroll
        for (int n = 0; n < 16; n++) {
            int col = n * 8 + (lane & 3) * 2;
            __half2 hp = __floats2half2_rn(O[n][rr * 2] * inv,
                                           O[n][rr * 2 + 1] * inv);
            *(uint32_t*)(yhi + rb + col) = *(uint32_t*)&hp;
        }
    }
}

// ===========================================================================
// Launch
// ===========================================================================
extern "C" void kernel_launch(void* const* d_in, const int* in_sizes, int n_in,
                              void* d_out, int out_size)
{
    const float* x     = (const float*)d_in[0];
    const float* cosb  = (const float*)d_in[1];
    const float* sinb  = (const float*)d_in[2];
    const float* Wqkv  = (const float*)d_in[3];
    const float* Wproj = (const float*)d_in[4];
    float* out = (float*)d_out;

    float* qkv = nullptr;
    __half *atth, *ahi, *bhi;
    cudaGetSymbolAddress((void**)&qkv,  g_qkv);
    cudaGetSymbolAddress((void**)&atth, g_att);
    cudaGetSymbolAddress((void**)&ahi,  g_a_hi);
    cudaGetSymbolAddress((void**)&bhi,  g_b_hi);

    cudaFuncSetAttribute(hmma_gemm, cudaFuncAttributeMaxDynamicSharedMemorySize,
                         GEMM_SMEM);
    cudaFuncSetAttribute(attn_hmma, cudaFuncAttributeMaxDynamicSharedMemorySize,
                         ATT_SMEM);

    // ---- GEMM 1: qkv = x @ Wqkv^T ----
    {
        int n8a = M_ * C_ / 8, n8b = NQKV_ * C_ / 8;
        convert_f16_kernel<<<(n8a + 255) / 256, 256>>>(x, ahi, n8a);
        convert_f16_kernel<<<(n8b + 255) / 256, 256>>>(Wqkv, bhi, n8b);
        hmma_gemm<<<dim3(M_ / BM, NQKV_ / BN), 256, GEMM_SMEM>>>(
            ahi, bhi, qkv, NQKV_, C_);
    }

    // ---- RoPE + fp16 conversion ----
    {
        int total = M_ * NG_ * 6 * 16;
        rope_f16_kernel<<<(total + 255) / 256, 256>>>(qkv, cosb, sinb, atth);
    }

    // ---- fp16 attention -> y (fp16 into GEMM2 A buffer) ----
    attn_hmma<<<dim3(T_ / 128, B_ * NH_), 256, ATT_SMEM>>>(atth, ahi);

    // ---- GEMM 2: out = y @ Wproj^T ----
    {
        int n8b = C_ * C_ / 8;
        convert_f16_kernel<<<(n8b + 255) / 256, 256>>>(Wproj, bhi, n8b);
        hmma_gemm<<<dim3(M_ / BM, C_ / BN), 256, GEMM_SMEM>>>(
            ahi, bhi, out, C_, C_);
    }
}